// round 13
// baseline (speedup 1.0000x reference)
#include <cuda_runtime.h>
#include <cuda_fp16.h>
#include <math.h>
#include <stddef.h>
#include <stdint.h>

#define NN 100000
#define DD 256
#define RR 4
#define TT 150000
#define HH 2

constexpr size_t ND  = (size_t)NN * DD;         // 25.6M floats
constexpr size_t RND = (size_t)RR * NN * DD;    // 102.4M floats

__device__ float  g_arena[5 * RND];
__device__ __half g_combh[(size_t)RR * DD * DD];
// half weights: resW | gateW | inW | outW | lin1W | lin2W
__device__ __half g_wh[65536 + 131072 + 196608 + 65536 + 131072 + 131072];

// ---------------- helpers ----------------------------------------------------
__device__ __forceinline__ float warp_sum(float v) {
#pragma unroll
    for (int o = 16; o; o >>= 1) v += __shfl_xor_sync(0xffffffffu, v, o);
    return v;
}
__device__ __forceinline__ float gelu_exact(float x) {
    return 0.5f * x * (1.0f + erff(x * 0.7071067811865475f));
}
__device__ __forceinline__ float fast_sigmoid(float x) {
    return __fdividef(1.f, 1.f + __expf(-x));
}
__device__ __forceinline__ float fast_tanh(float x) {
    return 2.f * fast_sigmoid(2.f * x) - 1.f;
}
__device__ __forceinline__ uint32_t sm2u32(const void* p) {
    uint32_t a;
    asm("{ .reg .u64 t; cvta.to.shared.u64 t, %1; cvt.u32.u64 %0, t; }"
        : "=r"(a) : "l"(p));
    return a;
}
__device__ __forceinline__ void mma_f16(float& c0, float& c1, float& c2, float& c3,
                                        uint32_t a0, uint32_t a1, uint32_t a2, uint32_t a3,
                                        uint32_t b0, uint32_t b1) {
    asm volatile(
        "mma.sync.aligned.m16n8k16.row.col.f32.f16.f16.f32 "
        "{%0,%1,%2,%3}, {%4,%5,%6,%7}, {%8,%9}, {%0,%1,%2,%3};"
        : "+f"(c0), "+f"(c1), "+f"(c2), "+f"(c3)
        : "r"(a0), "r"(a1), "r"(a2), "r"(a3), "r"(b0), "r"(b1));
}
__device__ __forceinline__ void cp16(uint32_t dst, const void* src, uint32_t sz) {
    asm volatile("cp.async.cg.shared.global [%0], [%1], 16, %2;"
                 :: "r"(dst), "l"(src), "r"(sz) : "memory");
}
__device__ __forceinline__ void red4(float* p, float4 v) {
    asm volatile("red.global.add.v4.f32 [%0], {%1,%2,%3,%4};"
                 :: "l"(p), "f"(v.x), "f"(v.y), "f"(v.z), "f"(v.w) : "memory");
}

// ---------------- FP16 GEMM (R8-proven mainloop): C = A @ B^T, fp32 accum ----
#define BM 128
#define BN 128
#define BKH 32                        /* k per tile (halves) */
#define NSTG 4
#define A_BY (BM * 80)                /* 10240 B */
#define STG_BY (2 * A_BY)             /* 20480 B */
#define GEMM_SMEM (NSTG * STG_BY)     /* 80 KB */

template <int TRIA, int ACT, int HOUT>
__global__ __launch_bounds__(256, 2)
void gemm_h(const __half* __restrict__ A, const __half* __restrict__ B,
            void* __restrict__ Cv, const float* __restrict__ bias,
            const int* __restrict__ tri, int triN,
            int M, int K, int lda, int ldb, int ldc)
{
    extern __shared__ uint32_t smw[];
    const int tid  = threadIdx.x;
    const int m0   = blockIdx.y * BM;   // row block on slow axis
    const int n0   = blockIdx.x * BN;   // col block fast -> A tile shared in L2
    const int w    = tid >> 5, lane = tid & 31;
    const int wm   = w >> 2;
    const int wn   = w & 3;
    const int g    = lane >> 2;
    const int c4   = lane & 3;
    const uint32_t sbase = sm2u32(smw);

    const int prow  = tid >> 1;
    const int pkq0  = (tid & 1) * 16;
    const int grA   = m0 + prow;
    int ti0 = 0, ti1 = 0, ti2 = 0;
    if (TRIA) {
        int s = (grA < M) ? grA : 0;
        ti0 = tri[s]; ti1 = tri[triN + s]; ti2 = tri[2 * triN + s];
    }

    float acc[4][4][4];
#pragma unroll
    for (int i = 0; i < 4; i++)
#pragma unroll
        for (int j = 0; j < 4; j++)
#pragma unroll
            for (int e = 0; e < 4; e++) acc[i][j][e] = 0.f;

    auto tria_ldg = [&](int i, int kk) -> uint4 {
        const int kq = pkq0 + i * 8;
        const uint4 q0 = *(const uint4*)(A + (size_t)ti0 * lda + kk + kq);
        const uint4 q1 = *(const uint4*)(A + (size_t)ti1 * lda + kk + kq);
        const uint4 q2 = *(const uint4*)(A + (size_t)ti2 * lda + kk + kq);
        uint4 r;
        const float th = 1.f / 3.f;
#pragma unroll
        for (int j = 0; j < 4; j++) {
            float2 f0 = __half22float2(((const __half2*)&q0)[j]);
            float2 f1 = __half22float2(((const __half2*)&q1)[j]);
            float2 f2 = __half22float2(((const __half2*)&q2)[j]);
            ((__half2*)&r)[j] = __floats2half2_rn((f0.x + f1.x + f2.x) * th,
                                                  (f0.y + f1.y + f2.y) * th);
        }
        return r;
    };
    auto sts_a = [&](int st, int i, uint4 v) {
        uint32_t dst = sbase + st * STG_BY + prow * 80 + (pkq0 + i * 8) * 2;
        asm volatile("st.shared.v4.b32 [%0], {%1,%2,%3,%4};"
                     :: "r"(dst), "r"(v.x), "r"(v.y), "r"(v.z), "r"(v.w) : "memory");
    };
    auto issue_tile = [&](int ct) {
        const int st = ct & (NSTG - 1);
        const uint32_t sb = sbase + st * STG_BY;
        const int kk = ct * BKH;
#pragma unroll
        for (int i = 0; i < 2; i++) {
            const int kq = pkq0 + i * 8;
            const uint32_t doff = prow * 80 + kq * 2;
            if (!TRIA) {
                const __half* sa = A + (size_t)((grA < M) ? grA : 0) * lda + kk + kq;
                cp16(sb + doff, sa, (grA < M) ? 16u : 0u);
            }
            const __half* sbp = B + (size_t)(n0 + prow) * ldb + kk + kq;
            cp16(sb + A_BY + doff, sbp, 16u);
        }
    };

    const int nt = K / BKH;
#pragma unroll
    for (int ct = 0; ct < NSTG - 1; ct++) {
        if (TRIA) { sts_a(ct, 0, tria_ldg(0, ct * BKH)); sts_a(ct, 1, tria_ldg(1, ct * BKH)); }
        issue_tile(ct);
        asm volatile("cp.async.commit_group;" ::: "memory");
    }

    for (int c = 0; c < nt; c++) {
        const int st = c & (NSTG - 1);
        uint4 tv0, tv1;
        const bool more = (c + NSTG - 1) < nt;
        if (TRIA && more) {
            tv0 = tria_ldg(0, (c + NSTG - 1) * BKH);
            tv1 = tria_ldg(1, (c + NSTG - 1) * BKH);
        }
        asm volatile("cp.async.wait_group %0;" :: "n"(NSTG - 2) : "memory");
        __syncthreads();
        if (more) {
            const int wst = (c + NSTG - 1) & (NSTG - 1);
            if (TRIA) { sts_a(wst, 0, tv0); sts_a(wst, 1, tv1); }
            issue_tile(c + NSTG - 1);
        }
        asm volatile("cp.async.commit_group;" ::: "memory");

        const uint32_t* sA = smw + st * (STG_BY / 4);
        const uint32_t* sB = sA + (A_BY / 4);
#pragma unroll
        for (int kb2 = 0; kb2 < 16; kb2 += 8) {
            uint32_t af[4][4];
#pragma unroll
            for (int mf = 0; mf < 4; mf++) {
                const int mi = (wm * 64 + mf * 16 + g) * 20 + kb2 + c4;
                af[mf][0] = sA[mi];        af[mf][1] = sA[mi + 160];
                af[mf][2] = sA[mi + 4];    af[mf][3] = sA[mi + 164];
            }
#pragma unroll
            for (int nf = 0; nf < 4; nf++) {
                const int ni = (wn * 32 + nf * 8 + g) * 20 + kb2 + c4;
                const uint32_t b0 = sB[ni];
                const uint32_t b1 = sB[ni + 4];
#pragma unroll
                for (int mf = 0; mf < 4; mf++)
                    mma_f16(acc[mf][nf][0], acc[mf][nf][1], acc[mf][nf][2], acc[mf][nf][3],
                            af[mf][0], af[mf][1], af[mf][2], af[mf][3], b0, b1);
            }
        }
    }

    const bool hb = (bias != nullptr);
#pragma unroll
    for (int mf = 0; mf < 4; mf++) {
#pragma unroll
        for (int half = 0; half < 2; half++) {
            int gm = m0 + wm * 64 + mf * 16 + g + half * 8;
            if (gm >= M) continue;
#pragma unroll
            for (int nf = 0; nf < 4; nf++) {
                int col = wn * 32 + nf * 8 + c4 * 2;
                float v0 = acc[mf][nf][half * 2 + 0];
                float v1 = acc[mf][nf][half * 2 + 1];
                if (hb) { v0 += bias[n0 + col]; v1 += bias[n0 + col + 1]; }
                if (ACT == 1) { v0 = gelu_exact(v0); v1 = gelu_exact(v1); }
                if (HOUT) {
                    __half* cp = (__half*)Cv + (size_t)gm * ldc + n0 + col;
                    *(__half2*)cp = __floats2half2_rn(v0, v1);
                } else {
                    float* cp = (float*)Cv + (size_t)gm * ldc + n0 + col;
                    *(float2*)cp = make_float2(v0, v1);
                }
            }
        }
    }
}

// ---------------- comb[r] = half(tri_W[r] @ node_W[r]) -----------------------
__global__ void combw_kernel(const float* __restrict__ nodeW,
                             const float* __restrict__ triW,
                             __half* __restrict__ comb)
{
    __shared__ float Ts[16][16];
    __shared__ float Ns[16][17];
    int r  = blockIdx.z;
    int ii = blockIdx.y * 16 + threadIdx.y;
    int kk = blockIdx.x * 16 + threadIdx.x;
    const float* tw = triW  + (size_t)r * DD * DD;
    const float* nw = nodeW + (size_t)r * DD * DD;
    float s = 0.f;
    for (int j0 = 0; j0 < DD; j0 += 16) {
        Ts[threadIdx.y][threadIdx.x] = tw[(size_t)ii * DD + j0 + threadIdx.x];
        Ns[threadIdx.y][threadIdx.x] = nw[(size_t)(j0 + threadIdx.y) * DD + kk];
        __syncthreads();
#pragma unroll
        for (int j = 0; j < 16; j++) s = fmaf(Ts[threadIdx.y][j], Ns[j][threadIdx.x], s);
        __syncthreads();
    }
    comb[((size_t)r * DD + ii) * DD + kk] = __float2half_rn(s);
}

__global__ void tohalf_kernel(const float* __restrict__ src, __half* __restrict__ dst,
                              size_t n) {
    size_t i = (size_t)blockIdx.x * blockDim.x + threadIdx.x;
    if (i < n) dst[i] = __float2half_rn(src[i]);
}

// ---------------- scatter: float4 loads + red.global.add.v4.f32 --------------
__global__ void scatter_kernel(const float* __restrict__ tmsg,
                               const int* __restrict__ tri,
                               float* __restrict__ nmsg, float* __restrict__ cnt)
{
    int gw   = (int)(((size_t)blockIdx.x * blockDim.x + threadIdx.x) >> 5);
    int lane = threadIdx.x & 31;
    if (gw >= TT) return;
    int t0 = tri[gw], t1 = tri[TT + gw], t2 = tri[2 * TT + gw];
    const float4* row = (const float4*)(tmsg + (size_t)gw * DD);
    float4 v0 = row[lane];
    float4 v1 = row[lane + 32];
    float* p0 = nmsg + (size_t)t0 * DD + lane * 4;
    float* p1 = nmsg + (size_t)t1 * DD + lane * 4;
    float* p2 = nmsg + (size_t)t2 * DD + lane * 4;
    red4(p0, v0); red4(p0 + 128, v1);
    red4(p1, v0); red4(p1 + 128, v1);
    red4(p2, v0); red4(p2 + 128, v1);
    if (lane == 0) {
        atomicAdd(cnt + t0, 1.f);
        atomicAdd(cnt + t1, 1.f);
        atomicAdd(cnt + t2, 1.f);
    }
}

__global__ void u_kernel(const float* __restrict__ nmsg,
                         const float* __restrict__ cnt, __half* __restrict__ u)
{
    size_t i = (size_t)blockIdx.x * blockDim.x + threadIdx.x;
    if (i >= ND) return;
    int n = (int)(i >> 8);
    float c = fmaxf(cnt[n], 1.f);
    float v = __fdividef(nmsg[i], c);
    u[i] = __float2half_rn(v > 0.f ? v : (__expf(v) - 1.f));    // ELU(alpha=1)
}

__global__ void h_kernel(const __half* __restrict__ u,
                         const __half* __restrict__ glog1, const __half* __restrict__ glog2,
                         const float* __restrict__ xres,
                         __half* __restrict__ dsth)
{
    size_t i = (size_t)blockIdx.x * blockDim.x + threadIdx.x;
    if (i >= ND) return;
    float a = fast_sigmoid(__half2float(glog1[i]) + __half2float(glog2[i]));
    float v = fast_tanh(__half2float(u[i])) * a + xres[i] * (1.f - a);
    dsth[i] = __float2half_rn(v);
}

// ---------------- attention over relation axis (R=4), half2-coalesced --------
__global__ void attn_kernel(const __half2* __restrict__ qkv2, __half2* __restrict__ oat2)
{
    size_t gt = (size_t)blockIdx.x * blockDim.x + threadIdx.x;
    int gw   = (int)(gt >> 5);
    int lane = threadIdx.x & 31;
    if (gw >= NN * HH) return;
    int n = gw >> 1, h = gw & 1;

    float2 q[4][2], k[4][2], v[4][2];
#pragma unroll
    for (int r = 0; r < RR; r++) {
        const __half2* base = qkv2 + ((size_t)r * NN + n) * 384 + h * 64 + lane;
#pragma unroll
        for (int e = 0; e < 2; e++) {
            q[r][e] = __half22float2(base[32 * e]);
            k[r][e] = __half22float2(base[128 + 32 * e]);
            v[r][e] = __half22float2(base[256 + 32 * e]);
        }
    }
    float s[4][4];
#pragma unroll
    for (int a = 0; a < 4; a++)
#pragma unroll
        for (int b = 0; b < 4; b++) {
            float p = 0.f;
#pragma unroll
            for (int e = 0; e < 2; e++) {
                p = fmaf(q[a][e].x, k[b][e].x, p);
                p = fmaf(q[a][e].y, k[b][e].y, p);
            }
            s[a][b] = warp_sum(p) * 0.08838834764831845f;  // 1/sqrt(128)
        }
#pragma unroll
    for (int a = 0; a < 4; a++) {
        float m = fmaxf(fmaxf(s[a][0], s[a][1]), fmaxf(s[a][2], s[a][3]));
        float p[4]; float sum = 0.f;
#pragma unroll
        for (int b = 0; b < 4; b++) { p[b] = __expf(s[a][b] - m); sum += p[b]; }
        float inv = __fdividef(1.f, sum);
        float2 o[2] = {make_float2(0.f, 0.f), make_float2(0.f, 0.f)};
#pragma unroll
        for (int b = 0; b < 4; b++) {
            float wgt = p[b] * inv;
#pragma unroll
            for (int e = 0; e < 2; e++) {
                o[e].x = fmaf(wgt, v[b][e].x, o[e].x);
                o[e].y = fmaf(wgt, v[b][e].y, o[e].y);
            }
        }
        __half2* dst = oat2 + ((size_t)a * NN + n) * 128 + h * 64 + lane;
#pragma unroll
        for (int e = 0; e < 2; e++)
            dst[32 * e] = __floats2half2_rn(o[e].x, o[e].y);
    }
}

// ---------------- LayerNorm(A+B) (both half) -> half out ----------------------
__global__ void ln_add_kernel(const __half* __restrict__ A, const __half* __restrict__ Bv,
                              const float* __restrict__ g, const float* __restrict__ bb,
                              __half* __restrict__ outh, size_t rows)
{
    size_t gt = (size_t)blockIdx.x * blockDim.x + threadIdx.x;
    size_t w  = gt >> 5;
    int lane  = threadIdx.x & 31;
    if (w >= rows) return;
    const __half* pa = A + w * DD;
    const __half* pb = Bv + w * DD;
    float y[8]; float s = 0.f;
#pragma unroll
    for (int e = 0; e < 8; e++) {
        int d = lane + 32 * e;
        y[e] = __half2float(pa[d]) + __half2float(pb[d]);
        s += y[e];
    }
    s = warp_sum(s);
    float mean = s * (1.f / DD);
    float vs = 0.f;
#pragma unroll
    for (int e = 0; e < 8; e++) { float dv = y[e] - mean; vs += dv * dv; }
    vs = warp_sum(vs);
    float inv = rsqrtf(vs * (1.f / DD) + 1e-5f);
    __half* ph = outh + w * DD;
#pragma unroll
    for (int e = 0; e < 8; e++) {
        int d = lane + 32 * e;
        ph[d] = __float2half_rn((y[e] - mean) * inv * g[d] + bb[d]);
    }
}

// ---------------- final: mean over R of LN(x1+ff2) ----------------------------
__global__ void final_kernel(const __half* __restrict__ x1, const __half* __restrict__ ff2,
                             const float* __restrict__ g, const float* __restrict__ bb,
                             float* __restrict__ out)
{
    size_t gt = (size_t)blockIdx.x * blockDim.x + threadIdx.x;
    size_t n  = gt >> 5;
    int lane  = threadIdx.x & 31;
    if (n >= NN) return;
    float acc[8];
#pragma unroll
    for (int e = 0; e < 8; e++) acc[e] = 0.f;
    for (int r = 0; r < RR; r++) {
        size_t off = ((size_t)r * NN + n) * DD;
        float y[8]; float s = 0.f;
#pragma unroll
        for (int e = 0; e < 8; e++) {
            int d = lane + 32 * e;
            y[e] = __half2float(x1[off + d]) + __half2float(ff2[off + d]);
            s += y[e];
        }
        s = warp_sum(s);
        float mean = s * (1.f / DD);
        float vs = 0.f;
#pragma unroll
        for (int e = 0; e < 8; e++) { float dv = y[e] - mean; vs += dv * dv; }
        vs = warp_sum(vs);
        float inv = rsqrtf(vs * (1.f / DD) + 1e-5f);
#pragma unroll
        for (int e = 0; e < 8; e++) {
            int d = lane + 32 * e;
            acc[e] += (y[e] - mean) * inv * g[d] + bb[d];
        }
    }
#pragma unroll
    for (int e = 0; e < 8; e++) out[n * DD + lane + 32 * e] = acc[e] * 0.25f;
}

// ---------------- launch ------------------------------------------------------
extern "C" void kernel_launch(void* const* d_in, const int* in_sizes, int n_in,
                              void* d_out, int out_size)
{
    const float* x     = (const float*)d_in[0];
    const int*   tris  = (const int*)  d_in[1];
    // d_in[2] = edge_index (unused)
    const float* nodeW = (const float*)d_in[3];
    const float* triW  = (const float*)d_in[4];
    const float* resW  = (const float*)d_in[5];
    const float* gateW = (const float*)d_in[6];
    const float* gateB = (const float*)d_in[7];
    const float* inW   = (const float*)d_in[8];
    const float* inB   = (const float*)d_in[9];
    const float* outW  = (const float*)d_in[10];
    const float* outB  = (const float*)d_in[11];
    const float* ln1g  = (const float*)d_in[12];
    const float* ln1b  = (const float*)d_in[13];
    const float* lin1W = (const float*)d_in[14];
    const float* lin1b = (const float*)d_in[15];
    const float* lin2W = (const float*)d_in[16];
    const float* lin2b = (const float*)d_in[17];
    const float* ln2g  = (const float*)d_in[18];
    const float* ln2b  = (const float*)d_in[19];
    float* out = (float*)d_out;

    float* arena;
    __half *combh, *wh;
    cudaGetSymbolAddress((void**)&arena, g_arena);
    cudaGetSymbolAddress((void**)&combh, g_combh);
    cudaGetSymbolAddress((void**)&wh,    g_wh);

    // ---- side stream + events (created once, host-side only) ----
    static cudaStream_t s1 = nullptr;
    static cudaEvent_t  eT[RR], eS[RR], eLast;
    if (s1 == nullptr) {
        cudaStreamCreateWithFlags(&s1, cudaStreamNonBlocking);
        for (int r = 0; r < RR; r++) {
            cudaEventCreateWithFlags(&eT[r], cudaEventDisableTiming);
            cudaEventCreateWithFlags(&eS[r], cudaEventDisableTiming);
        }
        cudaEventCreateWithFlags(&eLast, cudaEventDisableTiming);
    }

    // ---- aliased buffer map ----
    float* big = arena + RND;                    // 12*ND floats
    float* t2  = arena + 4 * RND;                // 4*ND floats
    // phase A (double-buffered per relation parity):
    float*  xres     = big;                          // ND
    float*  nmsg[2]  = { big + ND, big + 2 * ND };   // ND each
    float*  tmsg[2]  = { big + 3 * ND, big + 3 * ND + 3 * ND / 2 }; // 1.5*ND each
    float*  cnt[2]   = { big + 6 * ND, big + 6 * ND + NN };
    __half* u_h[2]   = { (__half*)(big + 13 * ND / 2),
                         (__half*)(big + 7 * ND) };  // ND halves each
    __half* glog2_h[2] = { (__half*)(big + 8 * ND),
                           (__half*)(big + 17 * ND / 2) };
    __half* glog1_h  = (__half*)(big + 15 * ND / 2);
    __half* x_h      = (__half*)(big + 9 * ND);
    // phase B:
    __half* qkv_h   = (__half*)big;                // 3*RND halves = [big, big+6*ND)
    __half* src_h   = (__half*)t2;                 // RND halves
    __half* oat_h   = (__half*)(t2 + 2 * ND);      // RND halves
    __half* oproj_h = (__half*)(big + 6 * ND);     // RND halves (disjoint from qkv)
    __half* x1_h    = (__half*)t2;                 // in-place over src_h
    __half* ff1_h   = (__half*)big;                // 2*RND halves
    __half* ff2_h   = (__half*)(big + 4 * ND);     // RND halves
    // half weights
    __half* resW_h  = wh;
    __half* gateW_h = wh + 65536;
    __half* inW_h   = gateW_h + 131072;
    __half* outW_h  = inW_h + 196608;
    __half* lin1W_h = outW_h + 65536;
    __half* lin2W_h = lin1W_h + 131072;

    cudaFuncSetAttribute(gemm_h<0, 0, 0>, cudaFuncAttributeMaxDynamicSharedMemorySize, GEMM_SMEM);
    cudaFuncSetAttribute(gemm_h<1, 0, 0>, cudaFuncAttributeMaxDynamicSharedMemorySize, GEMM_SMEM);
    cudaFuncSetAttribute(gemm_h<0, 0, 1>, cudaFuncAttributeMaxDynamicSharedMemorySize, GEMM_SMEM);
    cudaFuncSetAttribute(gemm_h<0, 1, 1>, cudaFuncAttributeMaxDynamicSharedMemorySize, GEMM_SMEM);

    dim3 blk(256);

    // operand conversions (main stream)
    tohalf_kernel<<<(unsigned)((ND + 255) / 256), blk>>>(x, x_h, ND);
    tohalf_kernel<<<256, blk>>>(resW,  resW_h,  65536);
    tohalf_kernel<<<512, blk>>>(gateW, gateW_h, 131072);
    tohalf_kernel<<<768, blk>>>(inW,   inW_h,   196608);
    tohalf_kernel<<<256, blk>>>(outW,  outW_h,  65536);
    tohalf_kernel<<<512, blk>>>(lin1W, lin1W_h, 131072);
    tohalf_kernel<<<512, blk>>>(lin2W, lin2W_h, 131072);
    combw_kernel<<<dim3(16, 16, RR), dim3(16, 16)>>>(nodeW, triW, combh);

    // initial zeroing of both parities (main stream, before fork)
    cudaMemsetAsync(nmsg[0], 0, ND * sizeof(float), 0);
    cudaMemsetAsync(nmsg[1], 0, ND * sizeof(float), 0);
    cudaMemsetAsync(cnt[0], 0, (size_t)NN * sizeof(float), 0);
    cudaMemsetAsync(cnt[1], 0, (size_t)NN * sizeof(float), 0);

    // xres (fp32) and relation-invariant gate half
    gemm_h<0, 0, 0><<<dim3(2, 782), blk, GEMM_SMEM>>>(
        x_h, resW_h, xres, nullptr, nullptr, 0, NN, DD, DD, DD, DD);
    gemm_h<0, 0, 1><<<dim3(2, 782), blk, GEMM_SMEM>>>(
        x_h, gateW_h, glog1_h, gateB, nullptr, 0, NN, DD, DD, 2 * DD, DD);

    // ---- pipelined relation loop: tri-GEMMs on main, rest on side stream ----
    for (int r = 0; r < RR; r++) {
        const int p = r & 1;
        const int* trir = tris + (size_t)r * 3 * TT;
        if (r >= 2) cudaStreamWaitEvent(0, eS[r - 2], 0);   // tmsg[p] free
        gemm_h<1, 0, 0><<<dim3(2, 1172), blk, GEMM_SMEM>>>(
            x_h, combh + (size_t)r * DD * DD, tmsg[p], nullptr, trir, TT,
            TT, DD, DD, DD, DD);
        cudaEventRecord(eT[r], 0);

        cudaStreamWaitEvent(s1, eT[r], 0);
        scatter_kernel<<<18750, blk, 0, s1>>>(tmsg[p], trir, nmsg[p], cnt[p]);
        cudaEventRecord(eS[r], s1);
        u_kernel<<<(unsigned)(ND / 256), blk, 0, s1>>>(nmsg[p], cnt[p], u_h[p]);
        // re-zero parity buffers for relation r+2
        cudaMemsetAsync(nmsg[p], 0, ND * sizeof(float), s1);
        cudaMemsetAsync(cnt[p], 0, (size_t)NN * sizeof(float), s1);
        gemm_h<0, 0, 1><<<dim3(2, 782), blk, GEMM_SMEM, s1>>>(
            u_h[p], gateW_h + DD, glog2_h[p], nullptr, nullptr, 0,
            NN, DD, DD, 2 * DD, DD);
        h_kernel<<<(unsigned)(ND / 256), blk, 0, s1>>>(
            u_h[p], glog1_h, glog2_h[p], xres, src_h + (size_t)r * ND);
        if (r == RR - 1) cudaEventRecord(eLast, s1);
    }
    cudaStreamWaitEvent(0, eLast, 0);   // join: all src_h written

    // ---- phase B (main stream, serial) ----
    gemm_h<0, 0, 1><<<dim3(6, 3125), blk, GEMM_SMEM>>>(
        src_h, inW_h, qkv_h, inB, nullptr, 0, RR * NN, DD, DD, DD, 3 * DD);
    attn_kernel<<<25000, blk>>>((const __half2*)qkv_h, (__half2*)oat_h);
    gemm_h<0, 0, 1><<<dim3(2, 3125), blk, GEMM_SMEM>>>(
        oat_h, outW_h, oproj_h, outB, nullptr, 0, RR * NN, DD, DD, DD, DD);
    ln_add_kernel<<<50000, blk>>>(src_h, oproj_h, ln1g, ln1b, x1_h, (size_t)RR * NN);
    gemm_h<0, 1, 1><<<dim3(4, 3125), blk, GEMM_SMEM>>>(
        x1_h, lin1W_h, ff1_h, lin1b, nullptr, 0, RR * NN, DD, DD, DD, 2 * DD);
    gemm_h<0, 0, 1><<<dim3(2, 3125), blk, GEMM_SMEM>>>(
        ff1_h, lin2W_h, ff2_h, lin2b, nullptr, 0, RR * NN, 2 * DD, 2 * DD, 2 * DD, DD);
    final_kernel<<<12500, blk>>>(x1_h, ff2_h, ln2g, ln2b, out);
}

// round 14
// speedup vs baseline: 1.0558x; 1.0558x over previous
#include <cuda_runtime.h>
#include <cuda_fp16.h>
#include <math.h>
#include <stddef.h>
#include <stdint.h>

#define NN 100000
#define DD 256
#define RR 4
#define TT 150000
#define HH 2

constexpr size_t ND  = (size_t)NN * DD;         // 25.6M floats
constexpr size_t RND = (size_t)RR * NN * DD;    // 102.4M floats

__device__ float  g_arena[5 * RND];
__device__ __half g_combh[(size_t)RR * DD * DD];
// half weights: resW | gateW | inW | outW | lin1W | lin2W
__device__ __half g_wh[65536 + 131072 + 196608 + 65536 + 131072 + 131072];

// ---------------- helpers ----------------------------------------------------
__device__ __forceinline__ float warp_sum(float v) {
#pragma unroll
    for (int o = 16; o; o >>= 1) v += __shfl_xor_sync(0xffffffffu, v, o);
    return v;
}
__device__ __forceinline__ float gelu_exact(float x) {
    return 0.5f * x * (1.0f + erff(x * 0.7071067811865475f));
}
__device__ __forceinline__ float fast_sigmoid(float x) {
    return __fdividef(1.f, 1.f + __expf(-x));
}
__device__ __forceinline__ float fast_tanh(float x) {
    return 2.f * fast_sigmoid(2.f * x) - 1.f;
}
__device__ __forceinline__ uint32_t sm2u32(const void* p) {
    uint32_t a;
    asm("{ .reg .u64 t; cvta.to.shared.u64 t, %1; cvt.u32.u64 %0, t; }"
        : "=r"(a) : "l"(p));
    return a;
}
__device__ __forceinline__ void mma_f16(float& c0, float& c1, float& c2, float& c3,
                                        uint32_t a0, uint32_t a1, uint32_t a2, uint32_t a3,
                                        uint32_t b0, uint32_t b1) {
    asm volatile(
        "mma.sync.aligned.m16n8k16.row.col.f32.f16.f16.f32 "
        "{%0,%1,%2,%3}, {%4,%5,%6,%7}, {%8,%9}, {%0,%1,%2,%3};"
        : "+f"(c0), "+f"(c1), "+f"(c2), "+f"(c3)
        : "r"(a0), "r"(a1), "r"(a2), "r"(a3), "r"(b0), "r"(b1));
}
__device__ __forceinline__ void cp16(uint32_t dst, const void* src, uint32_t sz) {
    asm volatile("cp.async.cg.shared.global [%0], [%1], 16, %2;"
                 :: "r"(dst), "l"(src), "r"(sz) : "memory");
}
__device__ __forceinline__ void red4(float* p, float4 v) {
    asm volatile("red.global.add.v4.f32 [%0], {%1,%2,%3,%4};"
                 :: "l"(p), "f"(v.x), "f"(v.y), "f"(v.z), "f"(v.w) : "memory");
}
__device__ __forceinline__ void ldsm4(uint32_t& r0, uint32_t& r1, uint32_t& r2, uint32_t& r3,
                                      uint32_t addr) {
    asm volatile("ldmatrix.sync.aligned.m8n8.x4.shared.b16 {%0,%1,%2,%3}, [%4];"
                 : "=r"(r0), "=r"(r1), "=r"(r2), "=r"(r3) : "r"(addr));
}

// ---------------- FP16 GEMM: C = A @ B^T, fp32 accum -------------------------
// R12 structure; ONLY change: fragment loads via ldmatrix.x4 (6 per k16 step
// instead of 24 scalar LDS). 80B pitch keeps every ldmatrix phase conflict-free.
#define BM 128
#define BN 128
#define BKH 32                        /* k per tile (halves) */
#define NSTG 4
#define A_BY (BM * 80)                /* 10240 B */
#define STG_BY (2 * A_BY)             /* 20480 B */
#define GEMM_SMEM (NSTG * STG_BY)     /* 80 KB */

template <int TRIA, int ACT, int HOUT>
__global__ __launch_bounds__(256, 2)
void gemm_h(const __half* __restrict__ A, const __half* __restrict__ B,
            void* __restrict__ Cv, const float* __restrict__ bias,
            const int* __restrict__ tri, int triN,
            int M, int K, int lda, int ldb, int ldc)
{
    extern __shared__ uint32_t smw[];
    const int tid  = threadIdx.x;
    const int m0   = blockIdx.y * BM;   // row block slow axis
    const int n0   = blockIdx.x * BN;   // col block fast axis (A-tile L2 reuse)
    const int w    = tid >> 5, lane = tid & 31;
    const int wm   = w >> 2;
    const int wn   = w & 3;
    const int g    = lane >> 2;
    const int c4   = lane & 3;
    const uint32_t sbase = sm2u32(smw);

    // ldmatrix lane address components (bytes within stage)
    const int lrow = (lane & 7) + ((lane >> 3) & 1) * 8;   // 0-7,8-15,0-7,8-15
    const int lchu = ((lane >> 4) & 1) * 16;               // k-lo / k-hi 16B
    const uint32_t aoff = (uint32_t)((wm * 64 + lrow) * 80 + lchu);
    const uint32_t boff = (uint32_t)(A_BY + (wn * 32 + lrow) * 80 + lchu);

    // producer: one row per thread, two 16B granules (8 halves each)
    const int prow  = tid >> 1;
    const int pkq0  = (tid & 1) * 16;
    const int grA   = m0 + prow;
    int ti0 = 0, ti1 = 0, ti2 = 0;
    if (TRIA) {
        int s = (grA < M) ? grA : 0;
        ti0 = tri[s]; ti1 = tri[triN + s]; ti2 = tri[2 * triN + s];
    }

    float acc[4][4][4];
#pragma unroll
    for (int i = 0; i < 4; i++)
#pragma unroll
        for (int j = 0; j < 4; j++)
#pragma unroll
            for (int e = 0; e < 4; e++) acc[i][j][e] = 0.f;

    auto tria_ldg = [&](int i, int kk) -> uint4 {
        const int kq = pkq0 + i * 8;
        const uint4 q0 = *(const uint4*)(A + (size_t)ti0 * lda + kk + kq);
        const uint4 q1 = *(const uint4*)(A + (size_t)ti1 * lda + kk + kq);
        const uint4 q2 = *(const uint4*)(A + (size_t)ti2 * lda + kk + kq);
        uint4 r;
        const float th = 1.f / 3.f;
#pragma unroll
        for (int j = 0; j < 4; j++) {
            float2 f0 = __half22float2(((const __half2*)&q0)[j]);
            float2 f1 = __half22float2(((const __half2*)&q1)[j]);
            float2 f2 = __half22float2(((const __half2*)&q2)[j]);
            ((__half2*)&r)[j] = __floats2half2_rn((f0.x + f1.x + f2.x) * th,
                                                  (f0.y + f1.y + f2.y) * th);
        }
        return r;
    };
    auto sts_a = [&](int st, int i, uint4 v) {
        uint32_t dst = sbase + st * STG_BY + prow * 80 + (pkq0 + i * 8) * 2;
        asm volatile("st.shared.v4.b32 [%0], {%1,%2,%3,%4};"
                     :: "r"(dst), "r"(v.x), "r"(v.y), "r"(v.z), "r"(v.w) : "memory");
    };
    auto issue_tile = [&](int ct) {
        const int st = ct & (NSTG - 1);
        const uint32_t sb = sbase + st * STG_BY;
        const int kk = ct * BKH;
#pragma unroll
        for (int i = 0; i < 2; i++) {
            const int kq = pkq0 + i * 8;
            const uint32_t doff = prow * 80 + kq * 2;
            if (!TRIA) {
                const __half* sa = A + (size_t)((grA < M) ? grA : 0) * lda + kk + kq;
                cp16(sb + doff, sa, (grA < M) ? 16u : 0u);
            }
            const __half* sbp = B + (size_t)(n0 + prow) * ldb + kk + kq;
            cp16(sb + A_BY + doff, sbp, 16u);
        }
    };

    const int nt = K / BKH;
#pragma unroll
    for (int ct = 0; ct < NSTG - 1; ct++) {
        if (TRIA) { sts_a(ct, 0, tria_ldg(0, ct * BKH)); sts_a(ct, 1, tria_ldg(1, ct * BKH)); }
        issue_tile(ct);
        asm volatile("cp.async.commit_group;" ::: "memory");
    }

    for (int c = 0; c < nt; c++) {
        const int st = c & (NSTG - 1);
        uint4 tv0, tv1;
        const bool more = (c + NSTG - 1) < nt;
        if (TRIA && more) {
            tv0 = tria_ldg(0, (c + NSTG - 1) * BKH);
            tv1 = tria_ldg(1, (c + NSTG - 1) * BKH);
        }
        asm volatile("cp.async.wait_group %0;" :: "n"(NSTG - 2) : "memory");
        __syncthreads();
        if (more) {
            const int wst = (c + NSTG - 1) & (NSTG - 1);
            if (TRIA) { sts_a(wst, 0, tv0); sts_a(wst, 1, tv1); }
            issue_tile(c + NSTG - 1);
        }
        asm volatile("cp.async.commit_group;" ::: "memory");

        const uint32_t stg = sbase + st * STG_BY;
#pragma unroll
        for (int kb2 = 0; kb2 < 16; kb2 += 8) {        // two k16 steps
            uint32_t af[4][4];
#pragma unroll
            for (int mf = 0; mf < 4; mf++)
                ldsm4(af[mf][0], af[mf][1], af[mf][2], af[mf][3],
                      stg + aoff + mf * 1280 + kb2 * 4);
            uint32_t bf[2][4];
#pragma unroll
            for (int nfp = 0; nfp < 2; nfp++)
                ldsm4(bf[nfp][0], bf[nfp][1], bf[nfp][2], bf[nfp][3],
                      stg + boff + nfp * 1280 + kb2 * 4);
#pragma unroll
            for (int nf = 0; nf < 4; nf++) {
                const uint32_t b0 = bf[nf >> 1][nf & 1];
                const uint32_t b1 = bf[nf >> 1][(nf & 1) + 2];
#pragma unroll
                for (int mf = 0; mf < 4; mf++)
                    mma_f16(acc[mf][nf][0], acc[mf][nf][1], acc[mf][nf][2], acc[mf][nf][3],
                            af[mf][0], af[mf][1], af[mf][2], af[mf][3], b0, b1);
            }
        }
    }

    const bool hb = (bias != nullptr);
#pragma unroll
    for (int mf = 0; mf < 4; mf++) {
#pragma unroll
        for (int half = 0; half < 2; half++) {
            int gm = m0 + wm * 64 + mf * 16 + g + half * 8;
            if (gm >= M) continue;
#pragma unroll
            for (int nf = 0; nf < 4; nf++) {
                int col = wn * 32 + nf * 8 + c4 * 2;
                float v0 = acc[mf][nf][half * 2 + 0];
                float v1 = acc[mf][nf][half * 2 + 1];
                if (hb) { v0 += bias[n0 + col]; v1 += bias[n0 + col + 1]; }
                if (ACT == 1) { v0 = gelu_exact(v0); v1 = gelu_exact(v1); }
                if (HOUT) {
                    __half* cp = (__half*)Cv + (size_t)gm * ldc + n0 + col;
                    *(__half2*)cp = __floats2half2_rn(v0, v1);
                } else {
                    float* cp = (float*)Cv + (size_t)gm * ldc + n0 + col;
                    *(float2*)cp = make_float2(v0, v1);
                }
            }
        }
    }
}

// ---------------- comb[r] = half(tri_W[r] @ node_W[r]) -----------------------
__global__ void combw_kernel(const float* __restrict__ nodeW,
                             const float* __restrict__ triW,
                             __half* __restrict__ comb)
{
    __shared__ float Ts[16][16];
    __shared__ float Ns[16][17];
    int r  = blockIdx.z;
    int ii = blockIdx.y * 16 + threadIdx.y;
    int kk = blockIdx.x * 16 + threadIdx.x;
    const float* tw = triW  + (size_t)r * DD * DD;
    const float* nw = nodeW + (size_t)r * DD * DD;
    float s = 0.f;
    for (int j0 = 0; j0 < DD; j0 += 16) {
        Ts[threadIdx.y][threadIdx.x] = tw[(size_t)ii * DD + j0 + threadIdx.x];
        Ns[threadIdx.y][threadIdx.x] = nw[(size_t)(j0 + threadIdx.y) * DD + kk];
        __syncthreads();
#pragma unroll
        for (int j = 0; j < 16; j++) s = fmaf(Ts[threadIdx.y][j], Ns[j][threadIdx.x], s);
        __syncthreads();
    }
    comb[((size_t)r * DD + ii) * DD + kk] = __float2half_rn(s);
}

__global__ void tohalf_kernel(const float* __restrict__ src, __half* __restrict__ dst,
                              size_t n) {
    size_t i = (size_t)blockIdx.x * blockDim.x + threadIdx.x;
    if (i < n) dst[i] = __float2half_rn(src[i]);
}

// ---------------- scatter: float4 loads + red.global.add.v4.f32 --------------
__global__ void scatter_kernel(const float* __restrict__ tmsg,
                               const int* __restrict__ tri,
                               float* __restrict__ nmsg, float* __restrict__ cnt)
{
    int gw   = (int)(((size_t)blockIdx.x * blockDim.x + threadIdx.x) >> 5);
    int lane = threadIdx.x & 31;
    if (gw >= TT) return;
    int t0 = tri[gw], t1 = tri[TT + gw], t2 = tri[2 * TT + gw];
    const float4* row = (const float4*)(tmsg + (size_t)gw * DD);
    float4 v0 = row[lane];
    float4 v1 = row[lane + 32];
    float* p0 = nmsg + (size_t)t0 * DD + lane * 4;
    float* p1 = nmsg + (size_t)t1 * DD + lane * 4;
    float* p2 = nmsg + (size_t)t2 * DD + lane * 4;
    red4(p0, v0); red4(p0 + 128, v1);
    red4(p1, v0); red4(p1 + 128, v1);
    red4(p2, v0); red4(p2 + 128, v1);
    if (lane == 0) {
        atomicAdd(cnt + t0, 1.f);
        atomicAdd(cnt + t1, 1.f);
        atomicAdd(cnt + t2, 1.f);
    }
}

__global__ void u_kernel(const float* __restrict__ nmsg,
                         const float* __restrict__ cnt, __half* __restrict__ u)
{
    size_t i = (size_t)blockIdx.x * blockDim.x + threadIdx.x;
    if (i >= ND) return;
    int n = (int)(i >> 8);
    float c = fmaxf(cnt[n], 1.f);
    float v = __fdividef(nmsg[i], c);
    u[i] = __float2half_rn(v > 0.f ? v : (__expf(v) - 1.f));    // ELU(alpha=1)
}

__global__ void h_kernel(const __half* __restrict__ u,
                         const __half* __restrict__ glog1, const __half* __restrict__ glog2,
                         const float* __restrict__ xres,
                         __half* __restrict__ dsth)
{
    size_t i = (size_t)blockIdx.x * blockDim.x + threadIdx.x;
    if (i >= ND) return;
    float a = fast_sigmoid(__half2float(glog1[i]) + __half2float(glog2[i]));
    float v = fast_tanh(__half2float(u[i])) * a + xres[i] * (1.f - a);
    dsth[i] = __float2half_rn(v);
}

// ---------------- attention over relation axis (R=4), half2-coalesced --------
__global__ void attn_kernel(const __half2* __restrict__ qkv2, __half2* __restrict__ oat2)
{
    size_t gt = (size_t)blockIdx.x * blockDim.x + threadIdx.x;
    int gw   = (int)(gt >> 5);
    int lane = threadIdx.x & 31;
    if (gw >= NN * HH) return;
    int n = gw >> 1, h = gw & 1;

    float2 q[4][2], k[4][2], v[4][2];
#pragma unroll
    for (int r = 0; r < RR; r++) {
        const __half2* base = qkv2 + ((size_t)r * NN + n) * 384 + h * 64 + lane;
#pragma unroll
        for (int e = 0; e < 2; e++) {
            q[r][e] = __half22float2(base[32 * e]);
            k[r][e] = __half22float2(base[128 + 32 * e]);
            v[r][e] = __half22float2(base[256 + 32 * e]);
        }
    }
    float s[4][4];
#pragma unroll
    for (int a = 0; a < 4; a++)
#pragma unroll
        for (int b = 0; b < 4; b++) {
            float p = 0.f;
#pragma unroll
            for (int e = 0; e < 2; e++) {
                p = fmaf(q[a][e].x, k[b][e].x, p);
                p = fmaf(q[a][e].y, k[b][e].y, p);
            }
            s[a][b] = warp_sum(p) * 0.08838834764831845f;  // 1/sqrt(128)
        }
#pragma unroll
    for (int a = 0; a < 4; a++) {
        float m = fmaxf(fmaxf(s[a][0], s[a][1]), fmaxf(s[a][2], s[a][3]));
        float p[4]; float sum = 0.f;
#pragma unroll
        for (int b = 0; b < 4; b++) { p[b] = __expf(s[a][b] - m); sum += p[b]; }
        float inv = __fdividef(1.f, sum);
        float2 o[2] = {make_float2(0.f, 0.f), make_float2(0.f, 0.f)};
#pragma unroll
        for (int b = 0; b < 4; b++) {
            float wgt = p[b] * inv;
#pragma unroll
            for (int e = 0; e < 2; e++) {
                o[e].x = fmaf(wgt, v[b][e].x, o[e].x);
                o[e].y = fmaf(wgt, v[b][e].y, o[e].y);
            }
        }
        __half2* dst = oat2 + ((size_t)a * NN + n) * 128 + h * 64 + lane;
#pragma unroll
        for (int e = 0; e < 2; e++)
            dst[32 * e] = __floats2half2_rn(o[e].x, o[e].y);
    }
}

// ---------------- LayerNorm(A+B) (both half) -> half out ----------------------
__global__ void ln_add_kernel(const __half* __restrict__ A, const __half* __restrict__ Bv,
                              const float* __restrict__ g, const float* __restrict__ bb,
                              __half* __restrict__ outh, size_t rows)
{
    size_t gt = (size_t)blockIdx.x * blockDim.x + threadIdx.x;
    size_t w  = gt >> 5;
    int lane  = threadIdx.x & 31;
    if (w >= rows) return;
    const __half* pa = A + w * DD;
    const __half* pb = Bv + w * DD;
    float y[8]; float s = 0.f;
#pragma unroll
    for (int e = 0; e < 8; e++) {
        int d = lane + 32 * e;
        y[e] = __half2float(pa[d]) + __half2float(pb[d]);
        s += y[e];
    }
    s = warp_sum(s);
    float mean = s * (1.f / DD);
    float vs = 0.f;
#pragma unroll
    for (int e = 0; e < 8; e++) { float dv = y[e] - mean; vs += dv * dv; }
    vs = warp_sum(vs);
    float inv = rsqrtf(vs * (1.f / DD) + 1e-5f);
    __half* ph = outh + w * DD;
#pragma unroll
    for (int e = 0; e < 8; e++) {
        int d = lane + 32 * e;
        ph[d] = __float2half_rn((y[e] - mean) * inv * g[d] + bb[d]);
    }
}

// ---------------- final: mean over R of LN(x1+ff2) ----------------------------
__global__ void final_kernel(const __half* __restrict__ x1, const __half* __restrict__ ff2,
                             const float* __restrict__ g, const float* __restrict__ bb,
                             float* __restrict__ out)
{
    size_t gt = (size_t)blockIdx.x * blockDim.x + threadIdx.x;
    size_t n  = gt >> 5;
    int lane  = threadIdx.x & 31;
    if (n >= NN) return;
    float acc[8];
#pragma unroll
    for (int e = 0; e < 8; e++) acc[e] = 0.f;
    for (int r = 0; r < RR; r++) {
        size_t off = ((size_t)r * NN + n) * DD;
        float y[8]; float s = 0.f;
#pragma unroll
        for (int e = 0; e < 8; e++) {
            int d = lane + 32 * e;
            y[e] = __half2float(x1[off + d]) + __half2float(ff2[off + d]);
            s += y[e];
        }
        s = warp_sum(s);
        float mean = s * (1.f / DD);
        float vs = 0.f;
#pragma unroll
        for (int e = 0; e < 8; e++) { float dv = y[e] - mean; vs += dv * dv; }
        vs = warp_sum(vs);
        float inv = rsqrtf(vs * (1.f / DD) + 1e-5f);
#pragma unroll
        for (int e = 0; e < 8; e++) {
            int d = lane + 32 * e;
            acc[e] += (y[e] - mean) * inv * g[d] + bb[d];
        }
    }
#pragma unroll
    for (int e = 0; e < 8; e++) out[n * DD + lane + 32 * e] = acc[e] * 0.25f;
}

// ---------------- launch ------------------------------------------------------
extern "C" void kernel_launch(void* const* d_in, const int* in_sizes, int n_in,
                              void* d_out, int out_size)
{
    const float* x     = (const float*)d_in[0];
    const int*   tris  = (const int*)  d_in[1];
    // d_in[2] = edge_index (unused)
    const float* nodeW = (const float*)d_in[3];
    const float* triW  = (const float*)d_in[4];
    const float* resW  = (const float*)d_in[5];
    const float* gateW = (const float*)d_in[6];
    const float* gateB = (const float*)d_in[7];
    const float* inW   = (const float*)d_in[8];
    const float* inB   = (const float*)d_in[9];
    const float* outW  = (const float*)d_in[10];
    const float* outB  = (const float*)d_in[11];
    const float* ln1g  = (const float*)d_in[12];
    const float* ln1b  = (const float*)d_in[13];
    const float* lin1W = (const float*)d_in[14];
    const float* lin1b = (const float*)d_in[15];
    const float* lin2W = (const float*)d_in[16];
    const float* lin2b = (const float*)d_in[17];
    const float* ln2g  = (const float*)d_in[18];
    const float* ln2b  = (const float*)d_in[19];
    float* out = (float*)d_out;

    float* arena;
    __half *combh, *wh;
    cudaGetSymbolAddress((void**)&arena, g_arena);
    cudaGetSymbolAddress((void**)&combh, g_combh);
    cudaGetSymbolAddress((void**)&wh,    g_wh);

    // ---- aliased buffer map (identical to R12) ----
    float* big   = arena + RND;                  // 12*ND floats
    float* t2    = arena + 4 * RND;              // 4*ND floats
    float*  xres    = big;                         // ND
    float*  nmsg    = big + ND;                    // ND
    float*  tmsg    = big + 2 * ND;                // 1.5*ND
    float*  cnt     = big + 7 * ND / 2;            // NN floats
    __half* u_h     = (__half*)(big + 4 * ND);     // ND halves
    __half* x_h     = (__half*)(big + 9 * ND / 2); // ND halves
    __half* glog1_h = (__half*)(big + 5 * ND);     // ND halves
    __half* glog2_h = (__half*)(big + 11 * ND / 2);// ND halves
    __half* qkv_h   = (__half*)big;                // 3*RND halves
    __half* src_h   = (__half*)t2;                 // RND halves
    __half* oat_h   = (__half*)(t2 + 2 * ND);      // RND halves
    __half* oproj_h = (__half*)(big + 6 * ND);     // RND halves
    __half* x1_h    = (__half*)t2;                 // in-place over src_h
    __half* ff1_h   = (__half*)big;                // 2*RND halves
    __half* ff2_h   = (__half*)(big + 4 * ND);     // RND halves
    __half* resW_h  = wh;
    __half* gateW_h = wh + 65536;
    __half* inW_h   = gateW_h + 131072;
    __half* outW_h  = inW_h + 196608;
    __half* lin1W_h = outW_h + 65536;
    __half* lin2W_h = lin1W_h + 131072;

    cudaFuncSetAttribute(gemm_h<0, 0, 0>, cudaFuncAttributeMaxDynamicSharedMemorySize, GEMM_SMEM);
    cudaFuncSetAttribute(gemm_h<1, 0, 0>, cudaFuncAttributeMaxDynamicSharedMemorySize, GEMM_SMEM);
    cudaFuncSetAttribute(gemm_h<0, 0, 1>, cudaFuncAttributeMaxDynamicSharedMemorySize, GEMM_SMEM);
    cudaFuncSetAttribute(gemm_h<0, 1, 1>, cudaFuncAttributeMaxDynamicSharedMemorySize, GEMM_SMEM);

    dim3 blk(256);

    tohalf_kernel<<<(unsigned)((ND + 255) / 256), blk>>>(x, x_h, ND);
    tohalf_kernel<<<256, blk>>>(resW,  resW_h,  65536);
    tohalf_kernel<<<512, blk>>>(gateW, gateW_h, 131072);
    tohalf_kernel<<<768, blk>>>(inW,   inW_h,   196608);
    tohalf_kernel<<<256, blk>>>(outW,  outW_h,  65536);
    tohalf_kernel<<<512, blk>>>(lin1W, lin1W_h, 131072);
    tohalf_kernel<<<512, blk>>>(lin2W, lin2W_h, 131072);
    combw_kernel<<<dim3(16, 16, RR), dim3(16, 16)>>>(nodeW, triW, combh);

    gemm_h<0, 0, 0><<<dim3(2, 782), blk, GEMM_SMEM>>>(
        x_h, resW_h, xres, nullptr, nullptr, 0, NN, DD, DD, DD, DD);
    gemm_h<0, 0, 1><<<dim3(2, 782), blk, GEMM_SMEM>>>(
        x_h, gateW_h, glog1_h, gateB, nullptr, 0, NN, DD, DD, 2 * DD, DD);

    for (int r = 0; r < RR; r++) {
        const int* trir = tris + (size_t)r * 3 * TT;
        cudaMemsetAsync(nmsg, 0, ND * sizeof(float), 0);
        cudaMemsetAsync(cnt, 0, (size_t)NN * sizeof(float), 0);
        gemm_h<1, 0, 0><<<dim3(2, 1172), blk, GEMM_SMEM>>>(
            x_h, combh + (size_t)r * DD * DD, tmsg, nullptr, trir, TT,
            TT, DD, DD, DD, DD);
        scatter_kernel<<<18750, blk>>>(tmsg, trir, nmsg, cnt);
        u_kernel<<<(unsigned)(ND / 256), blk>>>(nmsg, cnt, u_h);
        gemm_h<0, 0, 1><<<dim3(2, 782), blk, GEMM_SMEM>>>(
            u_h, gateW_h + DD, glog2_h, nullptr, nullptr, 0, NN, DD, DD, 2 * DD, DD);
        h_kernel<<<(unsigned)(ND / 256), blk>>>(u_h, glog1_h, glog2_h, xres,
                                                src_h + (size_t)r * ND);
    }

    gemm_h<0, 0, 1><<<dim3(6, 3125), blk, GEMM_SMEM>>>(
        src_h, inW_h, qkv_h, inB, nullptr, 0, RR * NN, DD, DD, DD, 3 * DD);
    attn_kernel<<<25000, blk>>>((const __half2*)qkv_h, (__half2*)oat_h);
    gemm_h<0, 0, 1><<<dim3(2, 3125), blk, GEMM_SMEM>>>(
        oat_h, outW_h, oproj_h, outB, nullptr, 0, RR * NN, DD, DD, DD, DD);
    ln_add_kernel<<<50000, blk>>>(src_h, oproj_h, ln1g, ln1b, x1_h, (size_t)RR * NN);
    gemm_h<0, 1, 1><<<dim3(4, 3125), blk, GEMM_SMEM>>>(
        x1_h, lin1W_h, ff1_h, lin1b, nullptr, 0, RR * NN, DD, DD, DD, 2 * DD);
    gemm_h<0, 0, 1><<<dim3(2, 3125), blk, GEMM_SMEM>>>(
        ff1_h, lin2W_h, ff2_h, lin2b, nullptr, 0, RR * NN, 2 * DD, 2 * DD, 2 * DD, DD);
    final_kernel<<<12500, blk>>>(x1_h, ff2_h, ln2g, ln2b, out);
}

// round 15
// speedup vs baseline: 1.0771x; 1.0201x over previous
#include <cuda_runtime.h>
#include <cuda_fp16.h>
#include <math.h>
#include <stddef.h>
#include <stdint.h>

#define NN 100000
#define DD 256
#define RR 4
#define TT 150000
#define HH 2

constexpr size_t ND  = (size_t)NN * DD;         // 25.6M floats
constexpr size_t RND = (size_t)RR * NN * DD;    // 102.4M floats

__device__ float  g_arena[5 * RND];
__device__ __half g_combh[(size_t)RR * DD * DD];
// half weights: resW | gateW | inW | outW | lin1W | lin2W
__device__ __half g_wh[65536 + 131072 + 196608 + 65536 + 131072 + 131072];

// ---------------- helpers ----------------------------------------------------
__device__ __forceinline__ float warp_sum(float v) {
#pragma unroll
    for (int o = 16; o; o >>= 1) v += __shfl_xor_sync(0xffffffffu, v, o);
    return v;
}
__device__ __forceinline__ float gelu_exact(float x) {
    return 0.5f * x * (1.0f + erff(x * 0.7071067811865475f));
}
__device__ __forceinline__ float fast_sigmoid(float x) {
    return __fdividef(1.f, 1.f + __expf(-x));
}
__device__ __forceinline__ float fast_tanh(float x) {
    return 2.f * fast_sigmoid(2.f * x) - 1.f;
}
__device__ __forceinline__ uint32_t sm2u32(const void* p) {
    uint32_t a;
    asm("{ .reg .u64 t; cvta.to.shared.u64 t, %1; cvt.u32.u64 %0, t; }"
        : "=r"(a) : "l"(p));
    return a;
}
__device__ __forceinline__ void mma_f16(float& c0, float& c1, float& c2, float& c3,
                                        uint32_t a0, uint32_t a1, uint32_t a2, uint32_t a3,
                                        uint32_t b0, uint32_t b1) {
    asm volatile(
        "mma.sync.aligned.m16n8k16.row.col.f32.f16.f16.f32 "
        "{%0,%1,%2,%3}, {%4,%5,%6,%7}, {%8,%9}, {%0,%1,%2,%3};"
        : "+f"(c0), "+f"(c1), "+f"(c2), "+f"(c3)
        : "r"(a0), "r"(a1), "r"(a2), "r"(a3), "r"(b0), "r"(b1));
}
__device__ __forceinline__ void cp16(uint32_t dst, const void* src, uint32_t sz) {
    asm volatile("cp.async.cg.shared.global [%0], [%1], 16, %2;"
                 :: "r"(dst), "l"(src), "r"(sz) : "memory");
}
__device__ __forceinline__ void red2(float* p, float v0, float v1) {
    asm volatile("red.global.add.v2.f32 [%0], {%1,%2};"
                 :: "l"(p), "f"(v0), "f"(v1) : "memory");
}
__device__ __forceinline__ void ldsm4(uint32_t& r0, uint32_t& r1, uint32_t& r2, uint32_t& r3,
                                      uint32_t addr) {
    asm volatile("ldmatrix.sync.aligned.m8n8.x4.shared.b16 {%0,%1,%2,%3}, [%4];"
                 : "=r"(r0), "=r"(r1), "=r"(r2), "=r"(r3) : "r"(addr));
}

// ---------------- FP16 GEMM: C = A @ B^T, fp32 accum -------------------------
// R14 mainloop (ldmatrix fragments). New SCAT mode: epilogue scatters each
// output row to its triangle's 3 node rows via red.global.add.v2.f32
// (eliminates the tmsg round trip + scatter kernel).
#define BM 128
#define BN 128
#define BKH 32                        /* k per tile (halves) */
#define NSTG 4
#define A_BY (BM * 80)                /* 10240 B */
#define STG_BY (2 * A_BY)             /* 20480 B */
#define GEMM_SMEM (NSTG * STG_BY)     /* 80 KB */

template <int TRIA, int ACT, int HOUT, int SCAT>
__global__ __launch_bounds__(256, 2)
void gemm_h(const __half* __restrict__ A, const __half* __restrict__ B,
            void* __restrict__ Cv, const float* __restrict__ bias,
            const int* __restrict__ tri, int triN,
            int M, int K, int lda, int ldb, int ldc)
{
    extern __shared__ uint32_t smw[];
    const int tid  = threadIdx.x;
    const int m0   = blockIdx.y * BM;   // row block slow axis
    const int n0   = blockIdx.x * BN;   // col block fast axis (A-tile L2 reuse)
    const int w    = tid >> 5, lane = tid & 31;
    const int wm   = w >> 2;
    const int wn   = w & 3;
    const int g    = lane >> 2;
    const int c4   = lane & 3;
    const uint32_t sbase = sm2u32(smw);

    // ldmatrix lane address components (bytes within stage)
    const int lrow = (lane & 7) + ((lane >> 3) & 1) * 8;
    const int lchu = ((lane >> 4) & 1) * 16;
    const uint32_t aoff = (uint32_t)((wm * 64 + lrow) * 80 + lchu);
    const uint32_t boff = (uint32_t)(A_BY + (wn * 32 + lrow) * 80 + lchu);

    // producer: one row per thread, two 16B granules (8 halves each)
    const int prow  = tid >> 1;
    const int pkq0  = (tid & 1) * 16;
    const int grA   = m0 + prow;
    int ti0 = 0, ti1 = 0, ti2 = 0;
    if (TRIA) {
        int s = (grA < M) ? grA : 0;
        ti0 = tri[s]; ti1 = tri[triN + s]; ti2 = tri[2 * triN + s];
    }

    float acc[4][4][4];
#pragma unroll
    for (int i = 0; i < 4; i++)
#pragma unroll
        for (int j = 0; j < 4; j++)
#pragma unroll
            for (int e = 0; e < 4; e++) acc[i][j][e] = 0.f;

    auto tria_ldg = [&](int i, int kk) -> uint4 {
        const int kq = pkq0 + i * 8;
        const uint4 q0 = *(const uint4*)(A + (size_t)ti0 * lda + kk + kq);
        const uint4 q1 = *(const uint4*)(A + (size_t)ti1 * lda + kk + kq);
        const uint4 q2 = *(const uint4*)(A + (size_t)ti2 * lda + kk + kq);
        uint4 r;
        const float th = 1.f / 3.f;
#pragma unroll
        for (int j = 0; j < 4; j++) {
            float2 f0 = __half22float2(((const __half2*)&q0)[j]);
            float2 f1 = __half22float2(((const __half2*)&q1)[j]);
            float2 f2 = __half22float2(((const __half2*)&q2)[j]);
            ((__half2*)&r)[j] = __floats2half2_rn((f0.x + f1.x + f2.x) * th,
                                                  (f0.y + f1.y + f2.y) * th);
        }
        return r;
    };
    auto sts_a = [&](int st, int i, uint4 v) {
        uint32_t dst = sbase + st * STG_BY + prow * 80 + (pkq0 + i * 8) * 2;
        asm volatile("st.shared.v4.b32 [%0], {%1,%2,%3,%4};"
                     :: "r"(dst), "r"(v.x), "r"(v.y), "r"(v.z), "r"(v.w) : "memory");
    };
    auto issue_tile = [&](int ct) {
        const int st = ct & (NSTG - 1);
        const uint32_t sb = sbase + st * STG_BY;
        const int kk = ct * BKH;
#pragma unroll
        for (int i = 0; i < 2; i++) {
            const int kq = pkq0 + i * 8;
            const uint32_t doff = prow * 80 + kq * 2;
            if (!TRIA) {
                const __half* sa = A + (size_t)((grA < M) ? grA : 0) * lda + kk + kq;
                cp16(sb + doff, sa, (grA < M) ? 16u : 0u);
            }
            const __half* sbp = B + (size_t)(n0 + prow) * ldb + kk + kq;
            cp16(sb + A_BY + doff, sbp, 16u);
        }
    };

    const int nt = K / BKH;
#pragma unroll
    for (int ct = 0; ct < NSTG - 1; ct++) {
        if (TRIA) { sts_a(ct, 0, tria_ldg(0, ct * BKH)); sts_a(ct, 1, tria_ldg(1, ct * BKH)); }
        issue_tile(ct);
        asm volatile("cp.async.commit_group;" ::: "memory");
    }

    for (int c = 0; c < nt; c++) {
        const int st = c & (NSTG - 1);
        uint4 tv0, tv1;
        const bool more = (c + NSTG - 1) < nt;
        if (TRIA && more) {
            tv0 = tria_ldg(0, (c + NSTG - 1) * BKH);
            tv1 = tria_ldg(1, (c + NSTG - 1) * BKH);
        }
        asm volatile("cp.async.wait_group %0;" :: "n"(NSTG - 2) : "memory");
        __syncthreads();
        if (more) {
            const int wst = (c + NSTG - 1) & (NSTG - 1);
            if (TRIA) { sts_a(wst, 0, tv0); sts_a(wst, 1, tv1); }
            issue_tile(c + NSTG - 1);
        }
        asm volatile("cp.async.commit_group;" ::: "memory");

        const uint32_t stg = sbase + st * STG_BY;
#pragma unroll
        for (int kb2 = 0; kb2 < 16; kb2 += 8) {        // two k16 steps
            uint32_t af[4][4];
#pragma unroll
            for (int mf = 0; mf < 4; mf++)
                ldsm4(af[mf][0], af[mf][1], af[mf][2], af[mf][3],
                      stg + aoff + mf * 1280 + kb2 * 4);
            uint32_t bf[2][4];
#pragma unroll
            for (int nfp = 0; nfp < 2; nfp++)
                ldsm4(bf[nfp][0], bf[nfp][1], bf[nfp][2], bf[nfp][3],
                      stg + boff + nfp * 1280 + kb2 * 4);
#pragma unroll
            for (int nf = 0; nf < 4; nf++) {
                const uint32_t b0 = bf[nf >> 1][nf & 1];
                const uint32_t b1 = bf[nf >> 1][(nf & 1) + 2];
#pragma unroll
                for (int mf = 0; mf < 4; mf++)
                    mma_f16(acc[mf][nf][0], acc[mf][nf][1], acc[mf][nf][2], acc[mf][nf][3],
                            af[mf][0], af[mf][1], af[mf][2], af[mf][3], b0, b1);
            }
        }
    }

    // --- epilogue ---
    const bool hb = (bias != nullptr);
#pragma unroll
    for (int mf = 0; mf < 4; mf++) {
#pragma unroll
        for (int half = 0; half < 2; half++) {
            int gm = m0 + wm * 64 + mf * 16 + g + half * 8;
            if (gm >= M) continue;
            if (SCAT) {
                // scatter row gm to its triangle's 3 node rows
                int t0 = tri[gm], t1 = tri[triN + gm], t2 = tri[2 * triN + gm];
                float* nm = (float*)Cv;
#pragma unroll
                for (int nf = 0; nf < 4; nf++) {
                    int col = n0 + wn * 32 + nf * 8 + c4 * 2;
                    float v0 = acc[mf][nf][half * 2 + 0];
                    float v1 = acc[mf][nf][half * 2 + 1];
                    red2(nm + (size_t)t0 * DD + col, v0, v1);
                    red2(nm + (size_t)t1 * DD + col, v0, v1);
                    red2(nm + (size_t)t2 * DD + col, v0, v1);
                }
                continue;
            }
#pragma unroll
            for (int nf = 0; nf < 4; nf++) {
                int col = wn * 32 + nf * 8 + c4 * 2;
                float v0 = acc[mf][nf][half * 2 + 0];
                float v1 = acc[mf][nf][half * 2 + 1];
                if (hb) { v0 += bias[n0 + col]; v1 += bias[n0 + col + 1]; }
                if (ACT == 1) { v0 = gelu_exact(v0); v1 = gelu_exact(v1); }
                if (HOUT) {
                    __half* cp = (__half*)Cv + (size_t)gm * ldc + n0 + col;
                    *(__half2*)cp = __floats2half2_rn(v0, v1);
                } else {
                    float* cp = (float*)Cv + (size_t)gm * ldc + n0 + col;
                    *(float2*)cp = make_float2(v0, v1);
                }
            }
        }
    }
}

// ---------------- counts: one thread per triangle ------------------------------
__global__ void cnt_kernel(const int* __restrict__ tri, float* __restrict__ cnt) {
    int i = blockIdx.x * blockDim.x + threadIdx.x;
    if (i >= TT) return;
    atomicAdd(cnt + tri[i], 1.f);
    atomicAdd(cnt + tri[TT + i], 1.f);
    atomicAdd(cnt + tri[2 * TT + i], 1.f);
}

// ---------------- comb[r] = half(tri_W[r] @ node_W[r]) -----------------------
__global__ void combw_kernel(const float* __restrict__ nodeW,
                             const float* __restrict__ triW,
                             __half* __restrict__ comb)
{
    __shared__ float Ts[16][16];
    __shared__ float Ns[16][17];
    int r  = blockIdx.z;
    int ii = blockIdx.y * 16 + threadIdx.y;
    int kk = blockIdx.x * 16 + threadIdx.x;
    const float* tw = triW  + (size_t)r * DD * DD;
    const float* nw = nodeW + (size_t)r * DD * DD;
    float s = 0.f;
    for (int j0 = 0; j0 < DD; j0 += 16) {
        Ts[threadIdx.y][threadIdx.x] = tw[(size_t)ii * DD + j0 + threadIdx.x];
        Ns[threadIdx.y][threadIdx.x] = nw[(size_t)(j0 + threadIdx.y) * DD + kk];
        __syncthreads();
#pragma unroll
        for (int j = 0; j < 16; j++) s = fmaf(Ts[threadIdx.y][j], Ns[j][threadIdx.x], s);
        __syncthreads();
    }
    comb[((size_t)r * DD + ii) * DD + kk] = __float2half_rn(s);
}

__global__ void tohalf_kernel(const float* __restrict__ src, __half* __restrict__ dst,
                              size_t n) {
    size_t i = (size_t)blockIdx.x * blockDim.x + threadIdx.x;
    if (i < n) dst[i] = __float2half_rn(src[i]);
}

__global__ void u_kernel(const float* __restrict__ nmsg,
                         const float* __restrict__ cnt, __half* __restrict__ u)
{
    size_t i = (size_t)blockIdx.x * blockDim.x + threadIdx.x;
    if (i >= ND) return;
    int n = (int)(i >> 8);
    float c = fmaxf(cnt[n], 1.f);
    float v = __fdividef(nmsg[i], c);
    u[i] = __float2half_rn(v > 0.f ? v : (__expf(v) - 1.f));    // ELU(alpha=1)
}

__global__ void h_kernel(const __half* __restrict__ u,
                         const __half* __restrict__ glog1, const __half* __restrict__ glog2,
                         const float* __restrict__ xres,
                         __half* __restrict__ dsth)
{
    size_t i = (size_t)blockIdx.x * blockDim.x + threadIdx.x;
    if (i >= ND) return;
    float a = fast_sigmoid(__half2float(glog1[i]) + __half2float(glog2[i]));
    float v = fast_tanh(__half2float(u[i])) * a + xres[i] * (1.f - a);
    dsth[i] = __float2half_rn(v);
}

// ---------------- attention over relation axis (R=4), half2-coalesced --------
__global__ void attn_kernel(const __half2* __restrict__ qkv2, __half2* __restrict__ oat2)
{
    size_t gt = (size_t)blockIdx.x * blockDim.x + threadIdx.x;
    int gw   = (int)(gt >> 5);
    int lane = threadIdx.x & 31;
    if (gw >= NN * HH) return;
    int n = gw >> 1, h = gw & 1;

    float2 q[4][2], k[4][2], v[4][2];
#pragma unroll
    for (int r = 0; r < RR; r++) {
        const __half2* base = qkv2 + ((size_t)r * NN + n) * 384 + h * 64 + lane;
#pragma unroll
        for (int e = 0; e < 2; e++) {
            q[r][e] = __half22float2(base[32 * e]);
            k[r][e] = __half22float2(base[128 + 32 * e]);
            v[r][e] = __half22float2(base[256 + 32 * e]);
        }
    }
    float s[4][4];
#pragma unroll
    for (int a = 0; a < 4; a++)
#pragma unroll
        for (int b = 0; b < 4; b++) {
            float p = 0.f;
#pragma unroll
            for (int e = 0; e < 2; e++) {
                p = fmaf(q[a][e].x, k[b][e].x, p);
                p = fmaf(q[a][e].y, k[b][e].y, p);
            }
            s[a][b] = warp_sum(p) * 0.08838834764831845f;  // 1/sqrt(128)
        }
#pragma unroll
    for (int a = 0; a < 4; a++) {
        float m = fmaxf(fmaxf(s[a][0], s[a][1]), fmaxf(s[a][2], s[a][3]));
        float p[4]; float sum = 0.f;
#pragma unroll
        for (int b = 0; b < 4; b++) { p[b] = __expf(s[a][b] - m); sum += p[b]; }
        float inv = __fdividef(1.f, sum);
        float2 o[2] = {make_float2(0.f, 0.f), make_float2(0.f, 0.f)};
#pragma unroll
        for (int b = 0; b < 4; b++) {
            float wgt = p[b] * inv;
#pragma unroll
            for (int e = 0; e < 2; e++) {
                o[e].x = fmaf(wgt, v[b][e].x, o[e].x);
                o[e].y = fmaf(wgt, v[b][e].y, o[e].y);
            }
        }
        __half2* dst = oat2 + ((size_t)a * NN + n) * 128 + h * 64 + lane;
#pragma unroll
        for (int e = 0; e < 2; e++)
            dst[32 * e] = __floats2half2_rn(o[e].x, o[e].y);
    }
}

// ---------------- LayerNorm(A+B) (both half) -> half out ----------------------
__global__ void ln_add_kernel(const __half* __restrict__ A, const __half* __restrict__ Bv,
                              const float* __restrict__ g, const float* __restrict__ bb,
                              __half* __restrict__ outh, size_t rows)
{
    size_t gt = (size_t)blockIdx.x * blockDim.x + threadIdx.x;
    size_t w  = gt >> 5;
    int lane  = threadIdx.x & 31;
    if (w >= rows) return;
    const __half* pa = A + w * DD;
    const __half* pb = Bv + w * DD;
    float y[8]; float s = 0.f;
#pragma unroll
    for (int e = 0; e < 8; e++) {
        int d = lane + 32 * e;
        y[e] = __half2float(pa[d]) + __half2float(pb[d]);
        s += y[e];
    }
    s = warp_sum(s);
    float mean = s * (1.f / DD);
    float vs = 0.f;
#pragma unroll
    for (int e = 0; e < 8; e++) { float dv = y[e] - mean; vs += dv * dv; }
    vs = warp_sum(vs);
    float inv = rsqrtf(vs * (1.f / DD) + 1e-5f);
    __half* ph = outh + w * DD;
#pragma unroll
    for (int e = 0; e < 8; e++) {
        int d = lane + 32 * e;
        ph[d] = __float2half_rn((y[e] - mean) * inv * g[d] + bb[d]);
    }
}

// ---------------- final: mean over R of LN(x1+ff2) ----------------------------
__global__ void final_kernel(const __half* __restrict__ x1, const __half* __restrict__ ff2,
                             const float* __restrict__ g, const float* __restrict__ bb,
                             float* __restrict__ out)
{
    size_t gt = (size_t)blockIdx.x * blockDim.x + threadIdx.x;
    size_t n  = gt >> 5;
    int lane  = threadIdx.x & 31;
    if (n >= NN) return;
    float acc[8];
#pragma unroll
    for (int e = 0; e < 8; e++) acc[e] = 0.f;
    for (int r = 0; r < RR; r++) {
        size_t off = ((size_t)r * NN + n) * DD;
        float y[8]; float s = 0.f;
#pragma unroll
        for (int e = 0; e < 8; e++) {
            int d = lane + 32 * e;
            y[e] = __half2float(x1[off + d]) + __half2float(ff2[off + d]);
            s += y[e];
        }
        s = warp_sum(s);
        float mean = s * (1.f / DD);
        float vs = 0.f;
#pragma unroll
        for (int e = 0; e < 8; e++) { float dv = y[e] - mean; vs += dv * dv; }
        vs = warp_sum(vs);
        float inv = rsqrtf(vs * (1.f / DD) + 1e-5f);
#pragma unroll
        for (int e = 0; e < 8; e++) {
            int d = lane + 32 * e;
            acc[e] += (y[e] - mean) * inv * g[d] + bb[d];
        }
    }
#pragma unroll
    for (int e = 0; e < 8; e++) out[n * DD + lane + 32 * e] = acc[e] * 0.25f;
}

// ---------------- launch ------------------------------------------------------
extern "C" void kernel_launch(void* const* d_in, const int* in_sizes, int n_in,
                              void* d_out, int out_size)
{
    const float* x     = (const float*)d_in[0];
    const int*   tris  = (const int*)  d_in[1];
    // d_in[2] = edge_index (unused)
    const float* nodeW = (const float*)d_in[3];
    const float* triW  = (const float*)d_in[4];
    const float* resW  = (const float*)d_in[5];
    const float* gateW = (const float*)d_in[6];
    const float* gateB = (const float*)d_in[7];
    const float* inW   = (const float*)d_in[8];
    const float* inB   = (const float*)d_in[9];
    const float* outW  = (const float*)d_in[10];
    const float* outB  = (const float*)d_in[11];
    const float* ln1g  = (const float*)d_in[12];
    const float* ln1b  = (const float*)d_in[13];
    const float* lin1W = (const float*)d_in[14];
    const float* lin1b = (const float*)d_in[15];
    const float* lin2W = (const float*)d_in[16];
    const float* lin2b = (const float*)d_in[17];
    const float* ln2g  = (const float*)d_in[18];
    const float* ln2b  = (const float*)d_in[19];
    float* out = (float*)d_out;

    float* arena;
    __half *combh, *wh;
    cudaGetSymbolAddress((void**)&arena, g_arena);
    cudaGetSymbolAddress((void**)&combh, g_combh);
    cudaGetSymbolAddress((void**)&wh,    g_wh);

    // ---- aliased buffer map ----
    float* big   = arena + RND;                  // 12*ND floats
    float* t2    = arena + 4 * RND;              // 4*ND floats
    float*  xres    = big;                         // ND
    float*  nmsg    = big + ND;                    // ND
    float*  cnt     = big + 2 * ND;                // NN floats
    __half* u_h     = (__half*)(big + 4 * ND);     // ND halves
    __half* x_h     = (__half*)(big + 9 * ND / 2); // ND halves
    __half* glog1_h = (__half*)(big + 5 * ND);     // ND halves
    __half* glog2_h = (__half*)(big + 11 * ND / 2);// ND halves
    __half* qkv_h   = (__half*)big;                // 3*RND halves
    __half* src_h   = (__half*)t2;                 // RND halves
    __half* oat_h   = (__half*)(t2 + 2 * ND);      // RND halves
    __half* oproj_h = (__half*)(big + 6 * ND);     // RND halves
    __half* x1_h    = (__half*)t2;                 // in-place over src_h
    __half* ff1_h   = (__half*)big;                // 2*RND halves
    __half* ff2_h   = (__half*)(big + 4 * ND);     // RND halves
    __half* resW_h  = wh;
    __half* gateW_h = wh + 65536;
    __half* inW_h   = gateW_h + 131072;
    __half* outW_h  = inW_h + 196608;
    __half* lin1W_h = outW_h + 65536;
    __half* lin2W_h = lin1W_h + 131072;

    cudaFuncSetAttribute(gemm_h<0, 0, 0, 0>, cudaFuncAttributeMaxDynamicSharedMemorySize, GEMM_SMEM);
    cudaFuncSetAttribute(gemm_h<1, 0, 0, 1>, cudaFuncAttributeMaxDynamicSharedMemorySize, GEMM_SMEM);
    cudaFuncSetAttribute(gemm_h<0, 0, 1, 0>, cudaFuncAttributeMaxDynamicSharedMemorySize, GEMM_SMEM);
    cudaFuncSetAttribute(gemm_h<0, 1, 1, 0>, cudaFuncAttributeMaxDynamicSharedMemorySize, GEMM_SMEM);

    dim3 blk(256);

    tohalf_kernel<<<(unsigned)((ND + 255) / 256), blk>>>(x, x_h, ND);
    tohalf_kernel<<<256, blk>>>(resW,  resW_h,  65536);
    tohalf_kernel<<<512, blk>>>(gateW, gateW_h, 131072);
    tohalf_kernel<<<768, blk>>>(inW,   inW_h,   196608);
    tohalf_kernel<<<256, blk>>>(outW,  outW_h,  65536);
    tohalf_kernel<<<512, blk>>>(lin1W, lin1W_h, 131072);
    tohalf_kernel<<<512, blk>>>(lin2W, lin2W_h, 131072);
    combw_kernel<<<dim3(16, 16, RR), dim3(16, 16)>>>(nodeW, triW, combh);

    gemm_h<0, 0, 0, 0><<<dim3(2, 782), blk, GEMM_SMEM>>>(
        x_h, resW_h, xres, nullptr, nullptr, 0, NN, DD, DD, DD, DD);
    gemm_h<0, 0, 1, 0><<<dim3(2, 782), blk, GEMM_SMEM>>>(
        x_h, gateW_h, glog1_h, gateB, nullptr, 0, NN, DD, DD, 2 * DD, DD);

    for (int r = 0; r < RR; r++) {
        const int* trir = tris + (size_t)r * 3 * TT;
        cudaMemsetAsync(nmsg, 0, ND * sizeof(float), 0);
        cudaMemsetAsync(cnt, 0, (size_t)NN * sizeof(float), 0);
        cnt_kernel<<<(TT + 255) / 256, blk>>>(trir, cnt);
        // tri-GEMM with fused scatter epilogue (writes directly into nmsg)
        gemm_h<1, 0, 0, 1><<<dim3(2, 1172), blk, GEMM_SMEM>>>(
            x_h, combh + (size_t)r * DD * DD, nmsg, nullptr, trir, TT,
            TT, DD, DD, DD, DD);
        u_kernel<<<(unsigned)(ND / 256), blk>>>(nmsg, cnt, u_h);
        gemm_h<0, 0, 1, 0><<<dim3(2, 782), blk, GEMM_SMEM>>>(
            u_h, gateW_h + DD, glog2_h, nullptr, nullptr, 0, NN, DD, DD, 2 * DD, DD);
        h_kernel<<<(unsigned)(ND / 256), blk>>>(u_h, glog1_h, glog2_h, xres,
                                                src_h + (size_t)r * ND);
    }

    gemm_h<0, 0, 1, 0><<<dim3(6, 3125), blk, GEMM_SMEM>>>(
        src_h, inW_h, qkv_h, inB, nullptr, 0, RR * NN, DD, DD, DD, 3 * DD);
    attn_kernel<<<25000, blk>>>((const __half2*)qkv_h, (__half2*)oat_h);
    gemm_h<0, 0, 1, 0><<<dim3(2, 3125), blk, GEMM_SMEM>>>(
        oat_h, outW_h, oproj_h, outB, nullptr, 0, RR * NN, DD, DD, DD, DD);
    ln_add_kernel<<<50000, blk>>>(src_h, oproj_h, ln1g, ln1b, x1_h, (size_t)RR * NN);
    gemm_h<0, 1, 1, 0><<<dim3(4, 3125), blk, GEMM_SMEM>>>(
        x1_h, lin1W_h, ff1_h, lin1b, nullptr, 0, RR * NN, DD, DD, DD, 2 * DD);
    gemm_h<0, 0, 1, 0><<<dim3(2, 3125), blk, GEMM_SMEM>>>(
        ff1_h, lin2W_h, ff2_h, lin2b, nullptr, 0, RR * NN, 2 * DD, 2 * DD, 2 * DD, DD);
    final_kernel<<<12500, blk>>>(x1_h, ff2_h, ln2g, ln2b, out);
}

// round 16
// speedup vs baseline: 1.0829x; 1.0054x over previous
#include <cuda_runtime.h>
#include <cuda_fp16.h>
#include <math.h>
#include <stddef.h>
#include <stdint.h>

#define NN 100000
#define DD 256
#define RR 4
#define TT 150000
#define HH 2

constexpr size_t ND  = (size_t)NN * DD;         // 25.6M floats
constexpr size_t RND = (size_t)RR * NN * DD;    // 102.4M floats

__device__ float  g_arena[5 * RND];
__device__ __half g_combh[(size_t)RR * DD * DD];
// half weights: resW | gateW | inW | outW | lin1W | lin2W
__device__ __half g_wh[65536 + 131072 + 196608 + 65536 + 131072 + 131072];

// ---------------- helpers ----------------------------------------------------
__device__ __forceinline__ float warp_sum(float v) {
#pragma unroll
    for (int o = 16; o; o >>= 1) v += __shfl_xor_sync(0xffffffffu, v, o);
    return v;
}
__device__ __forceinline__ float gelu_exact(float x) {
    return 0.5f * x * (1.0f + erff(x * 0.7071067811865475f));
}
__device__ __forceinline__ float fast_sigmoid(float x) {
    return __fdividef(1.f, 1.f + __expf(-x));
}
__device__ __forceinline__ float fast_tanh(float x) {
    return 2.f * fast_sigmoid(2.f * x) - 1.f;
}
__device__ __forceinline__ uint32_t sm2u32(const void* p) {
    uint32_t a;
    asm("{ .reg .u64 t; cvta.to.shared.u64 t, %1; cvt.u32.u64 %0, t; }"
        : "=r"(a) : "l"(p));
    return a;
}
__device__ __forceinline__ void mma_f16(float& c0, float& c1, float& c2, float& c3,
                                        uint32_t a0, uint32_t a1, uint32_t a2, uint32_t a3,
                                        uint32_t b0, uint32_t b1) {
    asm volatile(
        "mma.sync.aligned.m16n8k16.row.col.f32.f16.f16.f32 "
        "{%0,%1,%2,%3}, {%4,%5,%6,%7}, {%8,%9}, {%0,%1,%2,%3};"
        : "+f"(c0), "+f"(c1), "+f"(c2), "+f"(c3)
        : "r"(a0), "r"(a1), "r"(a2), "r"(a3), "r"(b0), "r"(b1));
}
__device__ __forceinline__ void cp16(uint32_t dst, const void* src, uint32_t sz) {
    asm volatile("cp.async.cg.shared.global [%0], [%1], 16, %2;"
                 :: "r"(dst), "l"(src), "r"(sz) : "memory");
}
__device__ __forceinline__ void red2(float* p, float v0, float v1) {
    asm volatile("red.global.add.v2.f32 [%0], {%1,%2};"
                 :: "l"(p), "f"(v0), "f"(v1) : "memory");
}
__device__ __forceinline__ void ldsm4(uint32_t& r0, uint32_t& r1, uint32_t& r2, uint32_t& r3,
                                      uint32_t addr) {
    asm volatile("ldmatrix.sync.aligned.m8n8.x4.shared.b16 {%0,%1,%2,%3}, [%4];"
                 : "=r"(r0), "=r"(r1), "=r"(r2), "=r"(r3) : "r"(addr));
}

// ---------------- FP16 GEMM (R15-proven): C = A @ B^T, fp32 accum ------------
#define BM 128
#define BN 128
#define BKH 32                        /* k per tile (halves) */
#define NSTG 4
#define A_BY (BM * 80)                /* 10240 B */
#define STG_BY (2 * A_BY)             /* 20480 B */
#define GEMM_SMEM (NSTG * STG_BY)     /* 80 KB */

template <int TRIA, int ACT, int HOUT, int SCAT>
__global__ __launch_bounds__(256, 2)
void gemm_h(const __half* __restrict__ A, const __half* __restrict__ B,
            void* __restrict__ Cv, const float* __restrict__ bias,
            const int* __restrict__ tri, int triN,
            int M, int K, int lda, int ldb, int ldc)
{
    extern __shared__ uint32_t smw[];
    const int tid  = threadIdx.x;
    const int m0   = blockIdx.y * BM;   // row block slow axis
    const int n0   = blockIdx.x * BN;   // col block fast axis (A-tile L2 reuse)
    const int w    = tid >> 5, lane = tid & 31;
    const int wm   = w >> 2;
    const int wn   = w & 3;
    const int g    = lane >> 2;
    const int c4   = lane & 3;
    const uint32_t sbase = sm2u32(smw);

    const int lrow = (lane & 7) + ((lane >> 3) & 1) * 8;
    const int lchu = ((lane >> 4) & 1) * 16;
    const uint32_t aoff = (uint32_t)((wm * 64 + lrow) * 80 + lchu);
    const uint32_t boff = (uint32_t)(A_BY + (wn * 32 + lrow) * 80 + lchu);

    const int prow  = tid >> 1;
    const int pkq0  = (tid & 1) * 16;
    const int grA   = m0 + prow;
    int ti0 = 0, ti1 = 0, ti2 = 0;
    if (TRIA) {
        int s = (grA < M) ? grA : 0;
        ti0 = tri[s]; ti1 = tri[triN + s]; ti2 = tri[2 * triN + s];
    }

    float acc[4][4][4];
#pragma unroll
    for (int i = 0; i < 4; i++)
#pragma unroll
        for (int j = 0; j < 4; j++)
#pragma unroll
            for (int e = 0; e < 4; e++) acc[i][j][e] = 0.f;

    auto tria_ldg = [&](int i, int kk) -> uint4 {
        const int kq = pkq0 + i * 8;
        const uint4 q0 = *(const uint4*)(A + (size_t)ti0 * lda + kk + kq);
        const uint4 q1 = *(const uint4*)(A + (size_t)ti1 * lda + kk + kq);
        const uint4 q2 = *(const uint4*)(A + (size_t)ti2 * lda + kk + kq);
        uint4 r;
        const float th = 1.f / 3.f;
#pragma unroll
        for (int j = 0; j < 4; j++) {
            float2 f0 = __half22float2(((const __half2*)&q0)[j]);
            float2 f1 = __half22float2(((const __half2*)&q1)[j]);
            float2 f2 = __half22float2(((const __half2*)&q2)[j]);
            ((__half2*)&r)[j] = __floats2half2_rn((f0.x + f1.x + f2.x) * th,
                                                  (f0.y + f1.y + f2.y) * th);
        }
        return r;
    };
    auto sts_a = [&](int st, int i, uint4 v) {
        uint32_t dst = sbase + st * STG_BY + prow * 80 + (pkq0 + i * 8) * 2;
        asm volatile("st.shared.v4.b32 [%0], {%1,%2,%3,%4};"
                     :: "r"(dst), "r"(v.x), "r"(v.y), "r"(v.z), "r"(v.w) : "memory");
    };
    auto issue_tile = [&](int ct) {
        const int st = ct & (NSTG - 1);
        const uint32_t sb = sbase + st * STG_BY;
        const int kk = ct * BKH;
#pragma unroll
        for (int i = 0; i < 2; i++) {
            const int kq = pkq0 + i * 8;
            const uint32_t doff = prow * 80 + kq * 2;
            if (!TRIA) {
                const __half* sa = A + (size_t)((grA < M) ? grA : 0) * lda + kk + kq;
                cp16(sb + doff, sa, (grA < M) ? 16u : 0u);
            }
            const __half* sbp = B + (size_t)(n0 + prow) * ldb + kk + kq;
            cp16(sb + A_BY + doff, sbp, 16u);
        }
    };

    const int nt = K / BKH;
#pragma unroll
    for (int ct = 0; ct < NSTG - 1; ct++) {
        if (TRIA) { sts_a(ct, 0, tria_ldg(0, ct * BKH)); sts_a(ct, 1, tria_ldg(1, ct * BKH)); }
        issue_tile(ct);
        asm volatile("cp.async.commit_group;" ::: "memory");
    }

    for (int c = 0; c < nt; c++) {
        const int st = c & (NSTG - 1);
        uint4 tv0, tv1;
        const bool more = (c + NSTG - 1) < nt;
        if (TRIA && more) {
            tv0 = tria_ldg(0, (c + NSTG - 1) * BKH);
            tv1 = tria_ldg(1, (c + NSTG - 1) * BKH);
        }
        asm volatile("cp.async.wait_group %0;" :: "n"(NSTG - 2) : "memory");
        __syncthreads();
        if (more) {
            const int wst = (c + NSTG - 1) & (NSTG - 1);
            if (TRIA) { sts_a(wst, 0, tv0); sts_a(wst, 1, tv1); }
            issue_tile(c + NSTG - 1);
        }
        asm volatile("cp.async.commit_group;" ::: "memory");

        const uint32_t stg = sbase + st * STG_BY;
#pragma unroll
        for (int kb2 = 0; kb2 < 16; kb2 += 8) {        // two k16 steps
            uint32_t af[4][4];
#pragma unroll
            for (int mf = 0; mf < 4; mf++)
                ldsm4(af[mf][0], af[mf][1], af[mf][2], af[mf][3],
                      stg + aoff + mf * 1280 + kb2 * 4);
            uint32_t bf[2][4];
#pragma unroll
            for (int nfp = 0; nfp < 2; nfp++)
                ldsm4(bf[nfp][0], bf[nfp][1], bf[nfp][2], bf[nfp][3],
                      stg + boff + nfp * 1280 + kb2 * 4);
#pragma unroll
            for (int nf = 0; nf < 4; nf++) {
                const uint32_t b0 = bf[nf >> 1][nf & 1];
                const uint32_t b1 = bf[nf >> 1][(nf & 1) + 2];
#pragma unroll
                for (int mf = 0; mf < 4; mf++)
                    mma_f16(acc[mf][nf][0], acc[mf][nf][1], acc[mf][nf][2], acc[mf][nf][3],
                            af[mf][0], af[mf][1], af[mf][2], af[mf][3], b0, b1);
            }
        }
    }

    // --- epilogue ---
    const bool hb = (bias != nullptr);
#pragma unroll
    for (int mf = 0; mf < 4; mf++) {
#pragma unroll
        for (int half = 0; half < 2; half++) {
            int gm = m0 + wm * 64 + mf * 16 + g + half * 8;
            if (gm >= M) continue;
            if (SCAT) {
                int t0 = tri[gm], t1 = tri[triN + gm], t2 = tri[2 * triN + gm];
                float* nm = (float*)Cv;
#pragma unroll
                for (int nf = 0; nf < 4; nf++) {
                    int col = n0 + wn * 32 + nf * 8 + c4 * 2;
                    float v0 = acc[mf][nf][half * 2 + 0];
                    float v1 = acc[mf][nf][half * 2 + 1];
                    red2(nm + (size_t)t0 * DD + col, v0, v1);
                    red2(nm + (size_t)t1 * DD + col, v0, v1);
                    red2(nm + (size_t)t2 * DD + col, v0, v1);
                }
                continue;
            }
#pragma unroll
            for (int nf = 0; nf < 4; nf++) {
                int col = wn * 32 + nf * 8 + c4 * 2;
                float v0 = acc[mf][nf][half * 2 + 0];
                float v1 = acc[mf][nf][half * 2 + 1];
                if (hb) { v0 += bias[n0 + col]; v1 += bias[n0 + col + 1]; }
                if (ACT == 1) { v0 = gelu_exact(v0); v1 = gelu_exact(v1); }
                if (HOUT) {
                    __half* cp = (__half*)Cv + (size_t)gm * ldc + n0 + col;
                    *(__half2*)cp = __floats2half2_rn(v0, v1);
                } else {
                    float* cp = (float*)Cv + (size_t)gm * ldc + n0 + col;
                    *(float2*)cp = make_float2(v0, v1);
                }
            }
        }
    }
}

// ---------------- counts for ALL relations: thread per (relation, triangle) ---
__global__ void cnt_kernel(const int* __restrict__ tris, float* __restrict__ cnt_all) {
    int i = blockIdx.x * blockDim.x + threadIdx.x;
    if (i >= RR * TT) return;
    int r = i / TT, t = i - r * TT;
    const int* tri = tris + (size_t)r * 3 * TT;
    float* cnt = cnt_all + (size_t)r * NN;
    atomicAdd(cnt + tri[t], 1.f);
    atomicAdd(cnt + tri[TT + t], 1.f);
    atomicAdd(cnt + tri[2 * TT + t], 1.f);
}

// ---------------- comb[r] = half(tri_W[r] @ node_W[r]) -----------------------
__global__ void combw_kernel(const float* __restrict__ nodeW,
                             const float* __restrict__ triW,
                             __half* __restrict__ comb)
{
    __shared__ float Ts[16][16];
    __shared__ float Ns[16][17];
    int r  = blockIdx.z;
    int ii = blockIdx.y * 16 + threadIdx.y;
    int kk = blockIdx.x * 16 + threadIdx.x;
    const float* tw = triW  + (size_t)r * DD * DD;
    const float* nw = nodeW + (size_t)r * DD * DD;
    float s = 0.f;
    for (int j0 = 0; j0 < DD; j0 += 16) {
        Ts[threadIdx.y][threadIdx.x] = tw[(size_t)ii * DD + j0 + threadIdx.x];
        Ns[threadIdx.y][threadIdx.x] = nw[(size_t)(j0 + threadIdx.y) * DD + kk];
        __syncthreads();
#pragma unroll
        for (int j = 0; j < 16; j++) s = fmaf(Ts[threadIdx.y][j], Ns[j][threadIdx.x], s);
        __syncthreads();
    }
    comb[((size_t)r * DD + ii) * DD + kk] = __float2half_rn(s);
}

__global__ void tohalf_kernel(const float* __restrict__ src, __half* __restrict__ dst,
                              size_t n) {
    size_t i = (size_t)blockIdx.x * blockDim.x + threadIdx.x;
    if (i < n) dst[i] = __float2half_rn(src[i]);
}

// ---------------- u over ALL relations: cnt indexed by global row -------------
__global__ void u_kernel(const float* __restrict__ nmsg_all,
                         const float* __restrict__ cnt_all, __half* __restrict__ u_all)
{
    size_t i = (size_t)blockIdx.x * blockDim.x + threadIdx.x;
    if (i >= RND) return;
    size_t row = i >> 8;                 // global row in [0, RR*NN)
    float c = fmaxf(cnt_all[row], 1.f);
    float v = __fdividef(nmsg_all[i], c);
    u_all[i] = __float2half_rn(v > 0.f ? v : (__expf(v) - 1.f));
}

// ---------------- h over ALL relations ----------------------------------------
__global__ void h_kernel(const __half* __restrict__ u_all,
                         const __half* __restrict__ glog1, const __half* __restrict__ glog2_all,
                         const float* __restrict__ xres,
                         __half* __restrict__ dsth_all)
{
    size_t i = (size_t)blockIdx.x * blockDim.x + threadIdx.x;
    if (i >= RND) return;
    size_t row = i >> 8;
    int col = (int)(i & 255);
    size_t n = row;                      // node id = row mod NN
    while (n >= NN) n -= NN;             // RR=4 small; cheap
    size_t ni = n * DD + col;
    float a = fast_sigmoid(__half2float(glog1[ni]) + __half2float(glog2_all[i]));
    float v = fast_tanh(__half2float(u_all[i])) * a + xres[ni] * (1.f - a);
    dsth_all[i] = __float2half_rn(v);
}

// ---------------- attention over relation axis (R=4), half2-coalesced --------
__global__ void attn_kernel(const __half2* __restrict__ qkv2, __half2* __restrict__ oat2)
{
    size_t gt = (size_t)blockIdx.x * blockDim.x + threadIdx.x;
    int gw   = (int)(gt >> 5);
    int lane = threadIdx.x & 31;
    if (gw >= NN * HH) return;
    int n = gw >> 1, h = gw & 1;

    float2 q[4][2], k[4][2], v[4][2];
#pragma unroll
    for (int r = 0; r < RR; r++) {
        const __half2* base = qkv2 + ((size_t)r * NN + n) * 384 + h * 64 + lane;
#pragma unroll
        for (int e = 0; e < 2; e++) {
            q[r][e] = __half22float2(base[32 * e]);
            k[r][e] = __half22float2(base[128 + 32 * e]);
            v[r][e] = __half22float2(base[256 + 32 * e]);
        }
    }
    float s[4][4];
#pragma unroll
    for (int a = 0; a < 4; a++)
#pragma unroll
        for (int b = 0; b < 4; b++) {
            float p = 0.f;
#pragma unroll
            for (int e = 0; e < 2; e++) {
                p = fmaf(q[a][e].x, k[b][e].x, p);
                p = fmaf(q[a][e].y, k[b][e].y, p);
            }
            s[a][b] = warp_sum(p) * 0.08838834764831845f;  // 1/sqrt(128)
        }
#pragma unroll
    for (int a = 0; a < 4; a++) {
        float m = fmaxf(fmaxf(s[a][0], s[a][1]), fmaxf(s[a][2], s[a][3]));
        float p[4]; float sum = 0.f;
#pragma unroll
        for (int b = 0; b < 4; b++) { p[b] = __expf(s[a][b] - m); sum += p[b]; }
        float inv = __fdividef(1.f, sum);
        float2 o[2] = {make_float2(0.f, 0.f), make_float2(0.f, 0.f)};
#pragma unroll
        for (int b = 0; b < 4; b++) {
            float wgt = p[b] * inv;
#pragma unroll
            for (int e = 0; e < 2; e++) {
                o[e].x = fmaf(wgt, v[b][e].x, o[e].x);
                o[e].y = fmaf(wgt, v[b][e].y, o[e].y);
            }
        }
        __half2* dst = oat2 + ((size_t)a * NN + n) * 128 + h * 64 + lane;
#pragma unroll
        for (int e = 0; e < 2; e++)
            dst[32 * e] = __floats2half2_rn(o[e].x, o[e].y);
    }
}

// ---------------- LayerNorm(A+B) (both half) -> half out ----------------------
__global__ void ln_add_kernel(const __half* __restrict__ A, const __half* __restrict__ Bv,
                              const float* __restrict__ g, const float* __restrict__ bb,
                              __half* __restrict__ outh, size_t rows)
{
    size_t gt = (size_t)blockIdx.x * blockDim.x + threadIdx.x;
    size_t w  = gt >> 5;
    int lane  = threadIdx.x & 31;
    if (w >= rows) return;
    const __half* pa = A + w * DD;
    const __half* pb = Bv + w * DD;
    float y[8]; float s = 0.f;
#pragma unroll
    for (int e = 0; e < 8; e++) {
        int d = lane + 32 * e;
        y[e] = __half2float(pa[d]) + __half2float(pb[d]);
        s += y[e];
    }
    s = warp_sum(s);
    float mean = s * (1.f / DD);
    float vs = 0.f;
#pragma unroll
    for (int e = 0; e < 8; e++) { float dv = y[e] - mean; vs += dv * dv; }
    vs = warp_sum(vs);
    float inv = rsqrtf(vs * (1.f / DD) + 1e-5f);
    __half* ph = outh + w * DD;
#pragma unroll
    for (int e = 0; e < 8; e++) {
        int d = lane + 32 * e;
        ph[d] = __float2half_rn((y[e] - mean) * inv * g[d] + bb[d]);
    }
}

// ---------------- final: mean over R of LN(x1+ff2) ----------------------------
__global__ void final_kernel(const __half* __restrict__ x1, const __half* __restrict__ ff2,
                             const float* __restrict__ g, const float* __restrict__ bb,
                             float* __restrict__ out)
{
    size_t gt = (size_t)blockIdx.x * blockDim.x + threadIdx.x;
    size_t n  = gt >> 5;
    int lane  = threadIdx.x & 31;
    if (n >= NN) return;
    float acc[8];
#pragma unroll
    for (int e = 0; e < 8; e++) acc[e] = 0.f;
    for (int r = 0; r < RR; r++) {
        size_t off = ((size_t)r * NN + n) * DD;
        float y[8]; float s = 0.f;
#pragma unroll
        for (int e = 0; e < 8; e++) {
            int d = lane + 32 * e;
            y[e] = __half2float(x1[off + d]) + __half2float(ff2[off + d]);
            s += y[e];
        }
        s = warp_sum(s);
        float mean = s * (1.f / DD);
        float vs = 0.f;
#pragma unroll
        for (int e = 0; e < 8; e++) { float dv = y[e] - mean; vs += dv * dv; }
        vs = warp_sum(vs);
        float inv = rsqrtf(vs * (1.f / DD) + 1e-5f);
#pragma unroll
        for (int e = 0; e < 8; e++) {
            int d = lane + 32 * e;
            acc[e] += (y[e] - mean) * inv * g[d] + bb[d];
        }
    }
#pragma unroll
    for (int e = 0; e < 8; e++) out[n * DD + lane + 32 * e] = acc[e] * 0.25f;
}

// ---------------- launch ------------------------------------------------------
extern "C" void kernel_launch(void* const* d_in, const int* in_sizes, int n_in,
                              void* d_out, int out_size)
{
    const float* x     = (const float*)d_in[0];
    const int*   tris  = (const int*)  d_in[1];
    // d_in[2] = edge_index (unused)
    const float* nodeW = (const float*)d_in[3];
    const float* triW  = (const float*)d_in[4];
    const float* resW  = (const float*)d_in[5];
    const float* gateW = (const float*)d_in[6];
    const float* gateB = (const float*)d_in[7];
    const float* inW   = (const float*)d_in[8];
    const float* inB   = (const float*)d_in[9];
    const float* outW  = (const float*)d_in[10];
    const float* outB  = (const float*)d_in[11];
    const float* ln1g  = (const float*)d_in[12];
    const float* ln1b  = (const float*)d_in[13];
    const float* lin1W = (const float*)d_in[14];
    const float* lin1b = (const float*)d_in[15];
    const float* lin2W = (const float*)d_in[16];
    const float* lin2b = (const float*)d_in[17];
    const float* ln2g  = (const float*)d_in[18];
    const float* ln2b  = (const float*)d_in[19];
    float* out = (float*)d_out;

    float* arena;
    __half *combh, *wh;
    cudaGetSymbolAddress((void**)&arena, g_arena);
    cudaGetSymbolAddress((void**)&combh, g_combh);
    cudaGetSymbolAddress((void**)&wh,    g_wh);

    // ---- aliased buffer map ----
    float* big = arena + RND;                    // 12*ND floats
    float* t2  = arena + 4 * RND;                // 4*ND floats
    // phase A (all relations at once):
    float*  xres     = big;                          // ND
    float*  nmsg_all = big + ND;                     // 4*ND  [ND, 5ND)
    float*  cnt_all  = big + 5 * ND;                 // RR*NN floats
    __half* u_all    = (__half*)(big + 11 * ND / 2); // RND halves [5.5, 7.5)
    __half* glog1_h  = (__half*)(big + 15 * ND / 2); // ND halves  [7.5, 8)
    __half* glog2_a  = (__half*)(big + 8 * ND);      // RND halves [8, 10)
    __half* x_h      = (__half*)(big + 10 * ND);     // ND halves  [10, 10.5)
    // phase B:
    __half* qkv_h   = (__half*)big;                // 3*RND halves [0, 6ND)
    __half* src_h   = (__half*)t2;                 // RND halves
    __half* oat_h   = (__half*)(t2 + 2 * ND);      // RND halves
    __half* oproj_h = (__half*)(big + 6 * ND);     // RND halves [6, 8)
    __half* x1_h    = (__half*)t2;                 // in-place over src_h
    __half* ff1_h   = (__half*)big;                // 2*RND halves [0, 4)
    __half* ff2_h   = (__half*)(big + 4 * ND);     // RND halves [4, 6)
    __half* resW_h  = wh;
    __half* gateW_h = wh + 65536;
    __half* inW_h   = gateW_h + 131072;
    __half* outW_h  = inW_h + 196608;
    __half* lin1W_h = outW_h + 65536;
    __half* lin2W_h = lin1W_h + 131072;

    cudaFuncSetAttribute(gemm_h<0, 0, 0, 0>, cudaFuncAttributeMaxDynamicSharedMemorySize, GEMM_SMEM);
    cudaFuncSetAttribute(gemm_h<1, 0, 0, 1>, cudaFuncAttributeMaxDynamicSharedMemorySize, GEMM_SMEM);
    cudaFuncSetAttribute(gemm_h<0, 0, 1, 0>, cudaFuncAttributeMaxDynamicSharedMemorySize, GEMM_SMEM);
    cudaFuncSetAttribute(gemm_h<0, 1, 1, 0>, cudaFuncAttributeMaxDynamicSharedMemorySize, GEMM_SMEM);

    dim3 blk(256);

    tohalf_kernel<<<(unsigned)((ND + 255) / 256), blk>>>(x, x_h, ND);
    tohalf_kernel<<<256, blk>>>(resW,  resW_h,  65536);
    tohalf_kernel<<<512, blk>>>(gateW, gateW_h, 131072);
    tohalf_kernel<<<768, blk>>>(inW,   inW_h,   196608);
    tohalf_kernel<<<256, blk>>>(outW,  outW_h,  65536);
    tohalf_kernel<<<512, blk>>>(lin1W, lin1W_h, 131072);
    tohalf_kernel<<<512, blk>>>(lin2W, lin2W_h, 131072);
    combw_kernel<<<dim3(16, 16, RR), dim3(16, 16)>>>(nodeW, triW, combh);

    cudaMemsetAsync(nmsg_all, 0, RND * sizeof(float), 0);
    cudaMemsetAsync(cnt_all, 0, (size_t)RR * NN * sizeof(float), 0);

    gemm_h<0, 0, 0, 0><<<dim3(2, 782), blk, GEMM_SMEM>>>(
        x_h, resW_h, xres, nullptr, nullptr, 0, NN, DD, DD, DD, DD);
    gemm_h<0, 0, 1, 0><<<dim3(2, 782), blk, GEMM_SMEM>>>(
        x_h, gateW_h, glog1_h, gateB, nullptr, 0, NN, DD, DD, 2 * DD, DD);

    // counts for all relations (one launch)
    cnt_kernel<<<(RR * TT + 255) / 256, blk>>>(tris, cnt_all);

    // 4 tri-GEMM-scatters back-to-back (independent tensor work)
    for (int r = 0; r < RR; r++) {
        const int* trir = tris + (size_t)r * 3 * TT;
        gemm_h<1, 0, 0, 1><<<dim3(2, 1172), blk, GEMM_SMEM>>>(
            x_h, combh + (size_t)r * DD * DD, nmsg_all + (size_t)r * ND,
            nullptr, trir, TT, TT, DD, DD, DD, DD);
    }

    // single u / gate / h over all relations
    u_kernel<<<(unsigned)(RND / 256), blk>>>(nmsg_all, cnt_all, u_all);
    gemm_h<0, 0, 1, 0><<<dim3(2, 3125), blk, GEMM_SMEM>>>(
        u_all, gateW_h + DD, glog2_a, nullptr, nullptr, 0,
        RR * NN, DD, DD, 2 * DD, DD);
    h_kernel<<<(unsigned)(RND / 256), blk>>>(u_all, glog1_h, glog2_a, xres, src_h);

    // ---- phase B ----
    gemm_h<0, 0, 1, 0><<<dim3(6, 3125), blk, GEMM_SMEM>>>(
        src_h, inW_h, qkv_h, inB, nullptr, 0, RR * NN, DD, DD, DD, 3 * DD);
    attn_kernel<<<25000, blk>>>((const __half2*)qkv_h, (__half2*)oat_h);
    gemm_h<0, 0, 1, 0><<<dim3(2, 3125), blk, GEMM_SMEM>>>(
        oat_h, outW_h, oproj_h, outB, nullptr, 0, RR * NN, DD, DD, DD, DD);
    ln_add_kernel<<<50000, blk>>>(src_h, oproj_h, ln1g, ln1b, x1_h, (size_t)RR * NN);
    gemm_h<0, 1, 1, 0><<<dim3(4, 3125), blk, GEMM_SMEM>>>(
        x1_h, lin1W_h, ff1_h, lin1b, nullptr, 0, RR * NN, DD, DD, DD, 2 * DD);
    gemm_h<0, 0, 1, 0><<<dim3(2, 3125), blk, GEMM_SMEM>>>(
        ff1_h, lin2W_h, ff2_h, lin2b, nullptr, 0, RR * NN, 2 * DD, 2 * DD, 2 * DD, DD);
    final_kernel<<<12500, blk>>>(x1_h, ff2_h, ln2g, ln2b, out);
}

// round 17
// speedup vs baseline: 1.0939x; 1.0102x over previous
#include <cuda_runtime.h>
#include <cuda_fp16.h>
#include <math.h>
#include <stddef.h>
#include <stdint.h>

#define NN 100000
#define DD 256
#define RR 4
#define TT 150000
#define HH 2
#define TRB 1172   /* row blocks per relation in tri-GEMM = ceil(TT/128) */

constexpr size_t ND  = (size_t)NN * DD;         // 25.6M floats
constexpr size_t RND = (size_t)RR * NN * DD;    // 102.4M floats

__device__ float  g_arena[5 * RND];
__device__ __half g_combh[(size_t)RR * DD * DD];
// half weights: resW | gateW | inW | outW | lin1W | lin2W | wcat(512x256)
__device__ __half g_wh[65536 + 131072 + 196608 + 65536 + 131072 + 131072 + 131072];
__device__ float  g_bcat[512];

// ---------------- helpers ----------------------------------------------------
__device__ __forceinline__ float warp_sum(float v) {
#pragma unroll
    for (int o = 16; o; o >>= 1) v += __shfl_xor_sync(0xffffffffu, v, o);
    return v;
}
__device__ __forceinline__ float gelu_exact(float x) {
    return 0.5f * x * (1.0f + erff(x * 0.7071067811865475f));
}
__device__ __forceinline__ float fast_sigmoid(float x) {
    return __fdividef(1.f, 1.f + __expf(-x));
}
__device__ __forceinline__ float fast_tanh(float x) {
    return 2.f * fast_sigmoid(2.f * x) - 1.f;
}
__device__ __forceinline__ uint32_t sm2u32(const void* p) {
    uint32_t a;
    asm("{ .reg .u64 t; cvta.to.shared.u64 t, %1; cvt.u32.u64 %0, t; }"
        : "=r"(a) : "l"(p));
    return a;
}
__device__ __forceinline__ void mma_f16(float& c0, float& c1, float& c2, float& c3,
                                        uint32_t a0, uint32_t a1, uint32_t a2, uint32_t a3,
                                        uint32_t b0, uint32_t b1) {
    asm volatile(
        "mma.sync.aligned.m16n8k16.row.col.f32.f16.f16.f32 "
        "{%0,%1,%2,%3}, {%4,%5,%6,%7}, {%8,%9}, {%0,%1,%2,%3};"
        : "+f"(c0), "+f"(c1), "+f"(c2), "+f"(c3)
        : "r"(a0), "r"(a1), "r"(a2), "r"(a3), "r"(b0), "r"(b1));
}
__device__ __forceinline__ void cp16(uint32_t dst, const void* src, uint32_t sz) {
    asm volatile("cp.async.cg.shared.global [%0], [%1], 16, %2;"
                 :: "r"(dst), "l"(src), "r"(sz) : "memory");
}
__device__ __forceinline__ void red2(float* p, float v0, float v1) {
    asm volatile("red.global.add.v2.f32 [%0], {%1,%2};"
                 :: "l"(p), "f"(v0), "f"(v1) : "memory");
}
__device__ __forceinline__ void ldsm4(uint32_t& r0, uint32_t& r1, uint32_t& r2, uint32_t& r3,
                                      uint32_t addr) {
    asm volatile("ldmatrix.sync.aligned.m8n8.x4.shared.b16 {%0,%1,%2,%3}, [%4];"
                 : "=r"(r0), "=r"(r1), "=r"(r2), "=r"(r3) : "r"(addr));
}

// ---------------- FP16 GEMM: C = A @ B^T, fp32 accum -------------------------
// TRIA==1 implies SCAT: one launch covers all RR relations; blockIdx.y encodes
// (relation, rowblock). B/C/tri pointers are per-relation bases + fixed strides.
#define BM 128
#define BN 128
#define BKH 32
#define NSTG 4
#define A_BY (BM * 80)                /* 10240 B */
#define STG_BY (2 * A_BY)             /* 20480 B */
#define GEMM_SMEM (NSTG * STG_BY)     /* 80 KB */

template <int TRIA, int ACT, int HOUT, int SCAT>
__global__ __launch_bounds__(256, 2)
void gemm_h(const __half* __restrict__ A, const __half* __restrict__ Bb,
            void* __restrict__ Cvb, const float* __restrict__ bias,
            const int* __restrict__ trib, int triN,
            int M, int K, int lda, int ldb, int ldc)
{
    extern __shared__ uint32_t smw[];
    const int tid  = threadIdx.x;
    int m0, rrel = 0;
    if (TRIA) {
        rrel = blockIdx.y / TRB;
        m0   = (blockIdx.y - rrel * TRB) * BM;
    } else {
        m0 = blockIdx.y * BM;
    }
    const __half* B   = TRIA ? Bb + (size_t)rrel * DD * DD : Bb;
    const int*    tri = TRIA ? trib + (size_t)rrel * 3 * TT : trib;
    void*         Cv  = TRIA ? (void*)((float*)Cvb + (size_t)rrel * ND) : Cvb;
    const int n0   = blockIdx.x * BN;
    const int w    = tid >> 5, lane = tid & 31;
    const int wm   = w >> 2;
    const int wn   = w & 3;
    const int g    = lane >> 2;
    const int c4   = lane & 3;
    const uint32_t sbase = sm2u32(smw);

    const int lrow = (lane & 7) + ((lane >> 3) & 1) * 8;
    const int lchu = ((lane >> 4) & 1) * 16;
    const uint32_t aoff = (uint32_t)((wm * 64 + lrow) * 80 + lchu);
    const uint32_t boff = (uint32_t)(A_BY + (wn * 32 + lrow) * 80 + lchu);

    const int prow  = tid >> 1;
    const int pkq0  = (tid & 1) * 16;
    const int grA   = m0 + prow;
    int ti0 = 0, ti1 = 0, ti2 = 0;
    if (TRIA) {
        int s = (grA < M) ? grA : 0;
        ti0 = tri[s]; ti1 = tri[triN + s]; ti2 = tri[2 * triN + s];
    }

    float acc[4][4][4];
#pragma unroll
    for (int i = 0; i < 4; i++)
#pragma unroll
        for (int j = 0; j < 4; j++)
#pragma unroll
            for (int e = 0; e < 4; e++) acc[i][j][e] = 0.f;

    auto tria_ldg = [&](int i, int kk) -> uint4 {
        const int kq = pkq0 + i * 8;
        const uint4 q0 = *(const uint4*)(A + (size_t)ti0 * lda + kk + kq);
        const uint4 q1 = *(const uint4*)(A + (size_t)ti1 * lda + kk + kq);
        const uint4 q2 = *(const uint4*)(A + (size_t)ti2 * lda + kk + kq);
        uint4 r;
        const float th = 1.f / 3.f;
#pragma unroll
        for (int j = 0; j < 4; j++) {
            float2 f0 = __half22float2(((const __half2*)&q0)[j]);
            float2 f1 = __half22float2(((const __half2*)&q1)[j]);
            float2 f2 = __half22float2(((const __half2*)&q2)[j]);
            ((__half2*)&r)[j] = __floats2half2_rn((f0.x + f1.x + f2.x) * th,
                                                  (f0.y + f1.y + f2.y) * th);
        }
        return r;
    };
    auto sts_a = [&](int st, int i, uint4 v) {
        uint32_t dst = sbase + st * STG_BY + prow * 80 + (pkq0 + i * 8) * 2;
        asm volatile("st.shared.v4.b32 [%0], {%1,%2,%3,%4};"
                     :: "r"(dst), "r"(v.x), "r"(v.y), "r"(v.z), "r"(v.w) : "memory");
    };
    auto issue_tile = [&](int ct) {
        const int st = ct & (NSTG - 1);
        const uint32_t sb = sbase + st * STG_BY;
        const int kk = ct * BKH;
#pragma unroll
        for (int i = 0; i < 2; i++) {
            const int kq = pkq0 + i * 8;
            const uint32_t doff = prow * 80 + kq * 2;
            if (!TRIA) {
                const __half* sa = A + (size_t)((grA < M) ? grA : 0) * lda + kk + kq;
                cp16(sb + doff, sa, (grA < M) ? 16u : 0u);
            }
            const __half* sbp = B + (size_t)(n0 + prow) * ldb + kk + kq;
            cp16(sb + A_BY + doff, sbp, 16u);
        }
    };

    const int nt = K / BKH;
#pragma unroll
    for (int ct = 0; ct < NSTG - 1; ct++) {
        if (TRIA) { sts_a(ct, 0, tria_ldg(0, ct * BKH)); sts_a(ct, 1, tria_ldg(1, ct * BKH)); }
        issue_tile(ct);
        asm volatile("cp.async.commit_group;" ::: "memory");
    }

    for (int c = 0; c < nt; c++) {
        const int st = c & (NSTG - 1);
        uint4 tv0, tv1;
        const bool more = (c + NSTG - 1) < nt;
        if (TRIA && more) {
            tv0 = tria_ldg(0, (c + NSTG - 1) * BKH);
            tv1 = tria_ldg(1, (c + NSTG - 1) * BKH);
        }
        asm volatile("cp.async.wait_group %0;" :: "n"(NSTG - 2) : "memory");
        __syncthreads();
        if (more) {
            const int wst = (c + NSTG - 1) & (NSTG - 1);
            if (TRIA) { sts_a(wst, 0, tv0); sts_a(wst, 1, tv1); }
            issue_tile(c + NSTG - 1);
        }
        asm volatile("cp.async.commit_group;" ::: "memory");

        const uint32_t stg = sbase + st * STG_BY;
#pragma unroll
        for (int kb2 = 0; kb2 < 16; kb2 += 8) {        // two k16 steps
            uint32_t af[4][4];
#pragma unroll
            for (int mf = 0; mf < 4; mf++)
                ldsm4(af[mf][0], af[mf][1], af[mf][2], af[mf][3],
                      stg + aoff + mf * 1280 + kb2 * 4);
            uint32_t bf[2][4];
#pragma unroll
            for (int nfp = 0; nfp < 2; nfp++)
                ldsm4(bf[nfp][0], bf[nfp][1], bf[nfp][2], bf[nfp][3],
                      stg + boff + nfp * 1280 + kb2 * 4);
#pragma unroll
            for (int nf = 0; nf < 4; nf++) {
                const uint32_t b0 = bf[nf >> 1][nf & 1];
                const uint32_t b1 = bf[nf >> 1][(nf & 1) + 2];
#pragma unroll
                for (int mf = 0; mf < 4; mf++)
                    mma_f16(acc[mf][nf][0], acc[mf][nf][1], acc[mf][nf][2], acc[mf][nf][3],
                            af[mf][0], af[mf][1], af[mf][2], af[mf][3], b0, b1);
            }
        }
    }

    // --- epilogue ---
    const bool hb = (bias != nullptr);
#pragma unroll
    for (int mf = 0; mf < 4; mf++) {
#pragma unroll
        for (int half = 0; half < 2; half++) {
            int gm = m0 + wm * 64 + mf * 16 + g + half * 8;
            if (gm >= M) continue;
            if (SCAT) {
                int t0 = tri[gm], t1 = tri[triN + gm], t2 = tri[2 * triN + gm];
                float* nm = (float*)Cv;
#pragma unroll
                for (int nf = 0; nf < 4; nf++) {
                    int col = n0 + wn * 32 + nf * 8 + c4 * 2;
                    float v0 = acc[mf][nf][half * 2 + 0];
                    float v1 = acc[mf][nf][half * 2 + 1];
                    red2(nm + (size_t)t0 * DD + col, v0, v1);
                    red2(nm + (size_t)t1 * DD + col, v0, v1);
                    red2(nm + (size_t)t2 * DD + col, v0, v1);
                }
                continue;
            }
#pragma unroll
            for (int nf = 0; nf < 4; nf++) {
                int col = wn * 32 + nf * 8 + c4 * 2;
                float v0 = acc[mf][nf][half * 2 + 0];
                float v1 = acc[mf][nf][half * 2 + 1];
                if (hb) { v0 += bias[n0 + col]; v1 += bias[n0 + col + 1]; }
                if (ACT == 1) { v0 = gelu_exact(v0); v1 = gelu_exact(v1); }
                if (HOUT) {
                    __half* cp = (__half*)Cv + (size_t)gm * ldc + n0 + col;
                    *(__half2*)cp = __floats2half2_rn(v0, v1);
                } else {
                    float* cp = (float*)Cv + (size_t)gm * ldc + n0 + col;
                    *(float2*)cp = make_float2(v0, v1);
                }
            }
        }
    }
}

// ---------------- counts for ALL relations ------------------------------------
__global__ void cnt_kernel(const int* __restrict__ tris, float* __restrict__ cnt_all) {
    int i = blockIdx.x * blockDim.x + threadIdx.x;
    if (i >= RR * TT) return;
    int r = i / TT, t = i - r * TT;
    const int* tri = tris + (size_t)r * 3 * TT;
    float* cnt = cnt_all + (size_t)r * NN;
    atomicAdd(cnt + tri[t], 1.f);
    atomicAdd(cnt + tri[TT + t], 1.f);
    atomicAdd(cnt + tri[2 * TT + t], 1.f);
}

// ---------------- comb[r] = half(tri_W[r] @ node_W[r]) -----------------------
__global__ void combw_kernel(const float* __restrict__ nodeW,
                             const float* __restrict__ triW,
                             __half* __restrict__ comb)
{
    __shared__ float Ts[16][16];
    __shared__ float Ns[16][17];
    int r  = blockIdx.z;
    int ii = blockIdx.y * 16 + threadIdx.y;
    int kk = blockIdx.x * 16 + threadIdx.x;
    const float* tw = triW  + (size_t)r * DD * DD;
    const float* nw = nodeW + (size_t)r * DD * DD;
    float s = 0.f;
    for (int j0 = 0; j0 < DD; j0 += 16) {
        Ts[threadIdx.y][threadIdx.x] = tw[(size_t)ii * DD + j0 + threadIdx.x];
        Ns[threadIdx.y][threadIdx.x] = nw[(size_t)(j0 + threadIdx.y) * DD + kk];
        __syncthreads();
#pragma unroll
        for (int j = 0; j < 16; j++) s = fmaf(Ts[threadIdx.y][j], Ns[j][threadIdx.x], s);
        __syncthreads();
    }
    comb[((size_t)r * DD + ii) * DD + kk] = __float2half_rn(s);
}

__global__ void tohalf_kernel(const float* __restrict__ src, __half* __restrict__ dst,
                              size_t n) {
    size_t i = (size_t)blockIdx.x * blockDim.x + threadIdx.x;
    if (i < n) dst[i] = __float2half_rn(src[i]);
}

// build wcat[512x256] = [resW ; gateW W1-part] (half) and bcat = [0...0, gateB]
__global__ void wcat_kernel(const float* __restrict__ resW,
                            const float* __restrict__ gateW,
                            const float* __restrict__ gateB,
                            __half* __restrict__ wcat, float* __restrict__ bcat)
{
    int i = blockIdx.x * blockDim.x + threadIdx.x;   // 131072 elems
    if (i >= 131072) return;
    int row = i >> 8, col = i & 255;
    float v = (row < 256) ? resW[(size_t)row * 256 + col]
                          : gateW[(size_t)(row - 256) * 512 + col];
    wcat[i] = __float2half_rn(v);
    if (i < 512) bcat[i] = (i < 256) ? 0.f : gateB[i - 256];
}

// ---------------- u over ALL relations ----------------------------------------
__global__ void u_kernel(const float* __restrict__ nmsg_all,
                         const float* __restrict__ cnt_all, __half* __restrict__ u_all)
{
    size_t i = (size_t)blockIdx.x * blockDim.x + threadIdx.x;
    if (i >= RND) return;
    size_t row = i >> 8;
    float c = fmaxf(cnt_all[row], 1.f);
    float v = __fdividef(nmsg_all[i], c);
    u_all[i] = __float2half_rn(v > 0.f ? v : (__expf(v) - 1.f));
}

// ---------------- h over ALL relations (xg = interleaved [xres|glog1] rows) ---
__global__ void h_kernel(const __half* __restrict__ u_all,
                         const __half* __restrict__ xg, const __half* __restrict__ glog2_all,
                         __half* __restrict__ dsth_all)
{
    size_t i = (size_t)blockIdx.x * blockDim.x + threadIdx.x;
    if (i >= RND) return;
    size_t row = i >> 8;
    int col = (int)(i & 255);
    size_t n = row;
    while (n >= NN) n -= NN;
    const __half* xr = xg + n * 512;
    float a = fast_sigmoid(__half2float(xr[256 + col]) + __half2float(glog2_all[i]));
    float v = fast_tanh(__half2float(u_all[i])) * a + __half2float(xr[col]) * (1.f - a);
    dsth_all[i] = __float2half_rn(v);
}

// ---------------- attention over relation axis (R=4), half2-coalesced --------
__global__ void attn_kernel(const __half2* __restrict__ qkv2, __half2* __restrict__ oat2)
{
    size_t gt = (size_t)blockIdx.x * blockDim.x + threadIdx.x;
    int gw   = (int)(gt >> 5);
    int lane = threadIdx.x & 31;
    if (gw >= NN * HH) return;
    int n = gw >> 1, h = gw & 1;

    float2 q[4][2], k[4][2], v[4][2];
#pragma unroll
    for (int r = 0; r < RR; r++) {
        const __half2* base = qkv2 + ((size_t)r * NN + n) * 384 + h * 64 + lane;
#pragma unroll
        for (int e = 0; e < 2; e++) {
            q[r][e] = __half22float2(base[32 * e]);
            k[r][e] = __half22float2(base[128 + 32 * e]);
            v[r][e] = __half22float2(base[256 + 32 * e]);
        }
    }
    float s[4][4];
#pragma unroll
    for (int a = 0; a < 4; a++)
#pragma unroll
        for (int b = 0; b < 4; b++) {
            float p = 0.f;
#pragma unroll
            for (int e = 0; e < 2; e++) {
                p = fmaf(q[a][e].x, k[b][e].x, p);
                p = fmaf(q[a][e].y, k[b][e].y, p);
            }
            s[a][b] = warp_sum(p) * 0.08838834764831845f;  // 1/sqrt(128)
        }
#pragma unroll
    for (int a = 0; a < 4; a++) {
        float m = fmaxf(fmaxf(s[a][0], s[a][1]), fmaxf(s[a][2], s[a][3]));
        float p[4]; float sum = 0.f;
#pragma unroll
        for (int b = 0; b < 4; b++) { p[b] = __expf(s[a][b] - m); sum += p[b]; }
        float inv = __fdividef(1.f, sum);
        float2 o[2] = {make_float2(0.f, 0.f), make_float2(0.f, 0.f)};
#pragma unroll
        for (int b = 0; b < 4; b++) {
            float wgt = p[b] * inv;
#pragma unroll
            for (int e = 0; e < 2; e++) {
                o[e].x = fmaf(wgt, v[b][e].x, o[e].x);
                o[e].y = fmaf(wgt, v[b][e].y, o[e].y);
            }
        }
        __half2* dst = oat2 + ((size_t)a * NN + n) * 128 + h * 64 + lane;
#pragma unroll
        for (int e = 0; e < 2; e++)
            dst[32 * e] = __floats2half2_rn(o[e].x, o[e].y);
    }
}

// ---------------- LayerNorm(A+B) (both half) -> half out ----------------------
__global__ void ln_add_kernel(const __half* __restrict__ A, const __half* __restrict__ Bv,
                              const float* __restrict__ g, const float* __restrict__ bb,
                              __half* __restrict__ outh, size_t rows)
{
    size_t gt = (size_t)blockIdx.x * blockDim.x + threadIdx.x;
    size_t w  = gt >> 5;
    int lane  = threadIdx.x & 31;
    if (w >= rows) return;
    const __half* pa = A + w * DD;
    const __half* pb = Bv + w * DD;
    float y[8]; float s = 0.f;
#pragma unroll
    for (int e = 0; e < 8; e++) {
        int d = lane + 32 * e;
        y[e] = __half2float(pa[d]) + __half2float(pb[d]);
        s += y[e];
    }
    s = warp_sum(s);
    float mean = s * (1.f / DD);
    float vs = 0.f;
#pragma unroll
    for (int e = 0; e < 8; e++) { float dv = y[e] - mean; vs += dv * dv; }
    vs = warp_sum(vs);
    float inv = rsqrtf(vs * (1.f / DD) + 1e-5f);
    __half* ph = outh + w * DD;
#pragma unroll
    for (int e = 0; e < 8; e++) {
        int d = lane + 32 * e;
        ph[d] = __float2half_rn((y[e] - mean) * inv * g[d] + bb[d]);
    }
}

// ---------------- final: mean over R of LN(x1+ff2) ----------------------------
__global__ void final_kernel(const __half* __restrict__ x1, const __half* __restrict__ ff2,
                             const float* __restrict__ g, const float* __restrict__ bb,
                             float* __restrict__ out)
{
    size_t gt = (size_t)blockIdx.x * blockDim.x + threadIdx.x;
    size_t n  = gt >> 5;
    int lane  = threadIdx.x & 31;
    if (n >= NN) return;
    float acc[8];
#pragma unroll
    for (int e = 0; e < 8; e++) acc[e] = 0.f;
    for (int r = 0; r < RR; r++) {
        size_t off = ((size_t)r * NN + n) * DD;
        float y[8]; float s = 0.f;
#pragma unroll
        for (int e = 0; e < 8; e++) {
            int d = lane + 32 * e;
            y[e] = __half2float(x1[off + d]) + __half2float(ff2[off + d]);
            s += y[e];
        }
        s = warp_sum(s);
        float mean = s * (1.f / DD);
        float vs = 0.f;
#pragma unroll
        for (int e = 0; e < 8; e++) { float dv = y[e] - mean; vs += dv * dv; }
        vs = warp_sum(vs);
        float inv = rsqrtf(vs * (1.f / DD) + 1e-5f);
#pragma unroll
        for (int e = 0; e < 8; e++) {
            int d = lane + 32 * e;
            acc[e] += (y[e] - mean) * inv * g[d] + bb[d];
        }
    }
#pragma unroll
    for (int e = 0; e < 8; e++) out[n * DD + lane + 32 * e] = acc[e] * 0.25f;
}

// ---------------- launch ------------------------------------------------------
extern "C" void kernel_launch(void* const* d_in, const int* in_sizes, int n_in,
                              void* d_out, int out_size)
{
    const float* x     = (const float*)d_in[0];
    const int*   tris  = (const int*)  d_in[1];
    // d_in[2] = edge_index (unused)
    const float* nodeW = (const float*)d_in[3];
    const float* triW  = (const float*)d_in[4];
    const float* resW  = (const float*)d_in[5];
    const float* gateW = (const float*)d_in[6];
    const float* gateB = (const float*)d_in[7];
    const float* inW   = (const float*)d_in[8];
    const float* inB   = (const float*)d_in[9];
    const float* outW  = (const float*)d_in[10];
    const float* outB  = (const float*)d_in[11];
    const float* ln1g  = (const float*)d_in[12];
    const float* ln1b  = (const float*)d_in[13];
    const float* lin1W = (const float*)d_in[14];
    const float* lin1b = (const float*)d_in[15];
    const float* lin2W = (const float*)d_in[16];
    const float* lin2b = (const float*)d_in[17];
    const float* ln2g  = (const float*)d_in[18];
    const float* ln2b  = (const float*)d_in[19];
    float* out = (float*)d_out;

    float *arena, *bcat;
    __half *combh, *wh;
    cudaGetSymbolAddress((void**)&arena, g_arena);
    cudaGetSymbolAddress((void**)&combh, g_combh);
    cudaGetSymbolAddress((void**)&wh,    g_wh);
    cudaGetSymbolAddress((void**)&bcat,  g_bcat);

    // ---- aliased buffer map ----
    float* big = arena + RND;                    // 12*ND floats
    float* t2  = arena + 4 * RND;                // 4*ND floats
    // phase A:
    __half* xg_h     = (__half*)big;                 // NN x 512 halves = ND floats [0,1)
    float*  nmsg_all = big + ND;                     // 4*ND  [1, 5)
    float*  cnt_all  = big + 5 * ND;                 // RR*NN floats
    __half* u_all    = (__half*)(big + 11 * ND / 2); // RND halves [5.5, 7.5)
    __half* glog2_a  = (__half*)(big + 8 * ND);      // RND halves [8, 10)
    __half* x_h      = (__half*)(big + 10 * ND);     // ND halves  [10, 10.5)
    // phase B:
    __half* qkv_h   = (__half*)big;                // 3*RND halves [0, 6ND)
    __half* src_h   = (__half*)t2;                 // RND halves
    __half* oat_h   = (__half*)(t2 + 2 * ND);      // RND halves
    __half* oproj_h = (__half*)(big + 6 * ND);     // RND halves [6, 8)
    __half* x1_h    = (__half*)t2;                 // in-place over src_h
    __half* ff1_h   = (__half*)big;                // 2*RND halves [0, 4)
    __half* ff2_h   = (__half*)(big + 4 * ND);     // RND halves [4, 6)
    __half* resW_h  = wh;
    __half* gateW_h = wh + 65536;
    __half* inW_h   = gateW_h + 131072;
    __half* outW_h  = inW_h + 196608;
    __half* lin1W_h = outW_h + 65536;
    __half* lin2W_h = lin1W_h + 131072;
    __half* wcat_h  = lin2W_h + 131072;

    cudaFuncSetAttribute(gemm_h<0, 0, 0, 0>, cudaFuncAttributeMaxDynamicSharedMemorySize, GEMM_SMEM);
    cudaFuncSetAttribute(gemm_h<1, 0, 0, 1>, cudaFuncAttributeMaxDynamicSharedMemorySize, GEMM_SMEM);
    cudaFuncSetAttribute(gemm_h<0, 0, 1, 0>, cudaFuncAttributeMaxDynamicSharedMemorySize, GEMM_SMEM);
    cudaFuncSetAttribute(gemm_h<0, 1, 1, 0>, cudaFuncAttributeMaxDynamicSharedMemorySize, GEMM_SMEM);

    dim3 blk(256);

    tohalf_kernel<<<(unsigned)((ND + 255) / 256), blk>>>(x, x_h, ND);
    tohalf_kernel<<<512, blk>>>(gateW, gateW_h, 131072);
    tohalf_kernel<<<768, blk>>>(inW,   inW_h,   196608);
    tohalf_kernel<<<256, blk>>>(outW,  outW_h,  65536);
    tohalf_kernel<<<512, blk>>>(lin1W, lin1W_h, 131072);
    tohalf_kernel<<<512, blk>>>(lin2W, lin2W_h, 131072);
    wcat_kernel<<<512, blk>>>(resW, gateW, gateB, wcat_h, bcat);
    combw_kernel<<<dim3(16, 16, RR), dim3(16, 16)>>>(nodeW, triW, combh);

    cudaMemsetAsync(nmsg_all, 0, RND * sizeof(float), 0);
    cudaMemsetAsync(cnt_all, 0, (size_t)RR * NN * sizeof(float), 0);

    // merged xres|glog1 GEMM: [NN, 512] half, rows interleaved per node
    gemm_h<0, 0, 1, 0><<<dim3(4, 782), blk, GEMM_SMEM>>>(
        x_h, wcat_h, xg_h, bcat, nullptr, 0, NN, DD, DD, DD, 512);

    // counts for all relations (one launch)
    cnt_kernel<<<(RR * TT + 255) / 256, blk>>>(tris, cnt_all);

    // ONE launch for all 4 tri-GEMM-scatters
    gemm_h<1, 0, 0, 1><<<dim3(2, RR * TRB), blk, GEMM_SMEM>>>(
        x_h, combh, nmsg_all, nullptr, tris, TT, TT, DD, DD, DD, DD);

    u_kernel<<<(unsigned)(RND / 256), blk>>>(nmsg_all, cnt_all, u_all);
    gemm_h<0, 0, 1, 0><<<dim3(2, 3125), blk, GEMM_SMEM>>>(
        u_all, gateW_h + DD, glog2_a, nullptr, nullptr, 0,
        RR * NN, DD, DD, 2 * DD, DD);
    h_kernel<<<(unsigned)(RND / 256), blk>>>(u_all, xg_h, glog2_a, src_h);

    // ---- phase B ----
    gemm_h<0, 0, 1, 0><<<dim3(6, 3125), blk, GEMM_SMEM>>>(
        src_h, inW_h, qkv_h, inB, nullptr, 0, RR * NN, DD, DD, DD, 3 * DD);
    attn_kernel<<<25000, blk>>>((const __half2*)qkv_h, (__half2*)oat_h);
    gemm_h<0, 0, 1, 0><<<dim3(2, 3125), blk, GEMM_SMEM>>>(
        oat_h, outW_h, oproj_h, outB, nullptr, 0, RR * NN, DD, DD, DD, DD);
    ln_add_kernel<<<50000, blk>>>(src_h, oproj_h, ln1g, ln1b, x1_h, (size_t)RR * NN);
    gemm_h<0, 1, 1, 0><<<dim3(4, 3125), blk, GEMM_SMEM>>>(
        x1_h, lin1W_h, ff1_h, lin1b, nullptr, 0, RR * NN, DD, DD, DD, 2 * DD);
    gemm_h<0, 0, 1, 0><<<dim3(2, 3125), blk, GEMM_SMEM>>>(
        ff1_h, lin2W_h, ff2_h, lin2b, nullptr, 0, RR * NN, 2 * DD, 2 * DD, 2 * DD, DD);
    final_kernel<<<12500, blk>>>(x1_h, ff2_h, ln2g, ln2b, out);
}